// round 2
// baseline (speedup 1.0000x reference)
#include <cuda_runtime.h>
#include <cstdint>
#include <cmath>

// Problem dims (fixed by the reference).
#define TT 512
#define BB 256
#define HH 512
#define G3 1536   // 3*HH

// Scratch for precomputed input-gate preactivations: [T*B, 3H] fp32 (805 MB).
// Device global => allocated at module load, no cudaMalloc (allocation-free rule).
__device__ float g_Xg[(size_t)TT * BB * G3];

__device__ __forceinline__ float sigmoidf_(float x) {
    return 1.0f / (1.0f + expf(-x));
}

// ----------------------------------------------------------------------------
// Kernel 1: Xg[t*B+b, gate*512+j] = sum_k ins[t,b,k] * W_i{gate}[k,j] + b_i{gate}[j]
// Classic 128x128 block tile, KT=8, 256 threads, 8x8 per thread (split 4+4).
// Grid: (M/128 = 1024, 12) where blockIdx.y selects gate (nb>>2) and 128-col slab.
// ----------------------------------------------------------------------------
__global__ __launch_bounds__(256) void input_gemm_kernel(
    const float* __restrict__ X,
    const float* __restrict__ Wr, const float* __restrict__ Wz, const float* __restrict__ Wn,
    const float* __restrict__ br, const float* __restrict__ bz, const float* __restrict__ bn)
{
    __shared__ float As[8][128];   // As[k][m] (transposed A tile)
    __shared__ float Bs[8][128];   // Bs[k][n]

    const int m0   = blockIdx.x * 128;
    const int nb   = blockIdx.y;            // 0..11
    const int gate = nb >> 2;                // 0:r 1:z 2:n
    const int j0   = (nb & 3) * 128;         // col offset within the gate

    const float* __restrict__ W    = (gate == 0) ? Wr : (gate == 1) ? Wz : Wn;
    const float* __restrict__ bias = (gate == 0) ? br : (gate == 1) ? bz : bn;

    const int tid   = threadIdx.x;
    const int a_row = tid >> 1;               // 0..127
    const int a_k   = (tid & 1) * 4;          // 0 or 4
    const int b_k   = tid >> 5;               // 0..7
    const int b_n   = (tid & 31) * 4;         // 0..124
    const int tx    = tid & 15;               // col group
    const int ty    = tid >> 4;               // row group

    float acc[8][8];
#pragma unroll
    for (int i = 0; i < 8; ++i)
#pragma unroll
        for (int j = 0; j < 8; ++j) acc[i][j] = 0.0f;

    for (int k0 = 0; k0 < HH; k0 += 8) {
        float4 av = *(const float4*)(X + (size_t)(m0 + a_row) * HH + k0 + a_k);
        float4 bv = *(const float4*)(W + (size_t)(k0 + b_k) * HH + j0 + b_n);
        As[a_k + 0][a_row] = av.x;
        As[a_k + 1][a_row] = av.y;
        As[a_k + 2][a_row] = av.z;
        As[a_k + 3][a_row] = av.w;
        *(float4*)&Bs[b_k][b_n] = bv;
        __syncthreads();

#pragma unroll
        for (int k = 0; k < 8; ++k) {
            float a[8], b[8];
            *(float4*)&a[0] = *(const float4*)&As[k][ty * 4];
            *(float4*)&a[4] = *(const float4*)&As[k][64 + ty * 4];
            *(float4*)&b[0] = *(const float4*)&Bs[k][tx * 4];
            *(float4*)&b[4] = *(const float4*)&Bs[k][64 + tx * 4];
#pragma unroll
            for (int i = 0; i < 8; ++i)
#pragma unroll
                for (int j = 0; j < 8; ++j)
                    acc[i][j] = fmaf(a[i], b[j], acc[i][j]);
        }
        __syncthreads();
    }

    // Epilogue: add bias, write to g_Xg.
    float4 bias_lo = *(const float4*)(bias + j0 + tx * 4);
    float4 bias_hi = *(const float4*)(bias + j0 + 64 + tx * 4);
#pragma unroll
    for (int i = 0; i < 8; ++i) {
        const int m_loc = (i < 4) ? (ty * 4 + i) : (64 + ty * 4 + (i - 4));
        float* orow = g_Xg + (size_t)(m0 + m_loc) * G3 + (size_t)gate * HH + j0;
        float4 v0, v1;
        v0.x = acc[i][0] + bias_lo.x;  v0.y = acc[i][1] + bias_lo.y;
        v0.z = acc[i][2] + bias_lo.z;  v0.w = acc[i][3] + bias_lo.w;
        v1.x = acc[i][4] + bias_hi.x;  v1.y = acc[i][5] + bias_hi.y;
        v1.z = acc[i][6] + bias_hi.z;  v1.w = acc[i][7] + bias_hi.w;
        *(float4*)(orow + tx * 4)      = v0;
        *(float4*)(orow + 64 + tx * 4) = v1;
    }
}

// ----------------------------------------------------------------------------
// Kernel 2: one GRU step. Fused GEMM over all 3 hidden gates + elementwise update.
//   G = h_eff @ [W_hr|W_hz|W_hn],  h_eff = reset ? 0 : h_{t-1}
//   r = sig(Xg_r + G_r); z = sig(Xg_z + G_z); n = tanh(Xg_n + r*(G_n + b_hn))
//   out[t] = (1-z)*n + z*h_eff
// CTA tile: 32 batch rows x (32 cols per gate = 96), KT=32, 128 threads,
// per-thread 4 rows x (2 cols x 3 gates). Warp layout tr=tid&7 for smem broadcast.
// Grid: (512/32 = 16 col blocks, 256/32 = 8 row blocks) = 128 CTAs.
// resets arrive as int32 (bool -> int32 per harness dtype conversion).
// ----------------------------------------------------------------------------
__global__ __launch_bounds__(128) void gru_step_kernel(
    const float* __restrict__ prev,        // h_{t-1}: [B,H] (init_h or out+(t-1)*B*H)
    const int* __restrict__ resets_t,      // [B] int32 flags for step t
    const float* __restrict__ Whr, const float* __restrict__ Whz,
    const float* __restrict__ Whn, const float* __restrict__ bhn,
    float* __restrict__ out_t,             // out + t*B*H
    int t)
{
    __shared__ float Hs[32][36];   // [k][row], padded, 16B-aligned rows
    __shared__ float Ws[32][96];   // [k][gate*32 + c]

    const int tid = threadIdx.x;
    const int j0  = blockIdx.x * 32;   // col block within a gate
    const int b0  = blockIdx.y * 32;   // batch row block
    const int tr  = tid & 7;           // row group (low bits -> broadcast in warp)
    const int tc  = tid >> 3;          // 0..15 col group
    const int r0  = tr * 4;
    const int c0  = tc * 2;

    const float* __restrict__ Xg_t = g_Xg + (size_t)t * BB * G3;

    float acc[4][6];
#pragma unroll
    for (int i = 0; i < 4; ++i)
#pragma unroll
        for (int j = 0; j < 6; ++j) acc[i][j] = 0.0f;

    for (int k0 = 0; k0 < HH; k0 += 32) {
        // Load h tile (transposed) with per-row reset masking.
#pragma unroll
        for (int q = 0; q < 2; ++q) {
            const int id = tid + q * 128;
            const int rr = id >> 3;           // 0..31
            const int kc = (id & 7) * 4;      // 0..28
            const float m = (resets_t[b0 + rr] != 0) ? 0.0f : 1.0f;
            float4 v = *(const float4*)(prev + (size_t)(b0 + rr) * HH + k0 + kc);
            Hs[kc + 0][rr] = v.x * m;
            Hs[kc + 1][rr] = v.y * m;
            Hs[kc + 2][rr] = v.z * m;
            Hs[kc + 3][rr] = v.w * m;
        }
        // Load W tiles for 3 gates.
#pragma unroll
        for (int q = 0; q < 2; ++q) {
            const int id  = tid + q * 128;
            const int kk  = id >> 3;          // 0..31
            const int cc4 = (id & 7) * 4;     // 0..28
            const size_t off = (size_t)(k0 + kk) * HH + j0 + cc4;
            *(float4*)&Ws[kk][ 0 + cc4] = *(const float4*)(Whr + off);
            *(float4*)&Ws[kk][32 + cc4] = *(const float4*)(Whz + off);
            *(float4*)&Ws[kk][64 + cc4] = *(const float4*)(Whn + off);
        }
        __syncthreads();

#pragma unroll 8
        for (int k = 0; k < 32; ++k) {
            float a[4], b[6];
            *(float4*)&a[0] = *(const float4*)&Hs[k][r0];
            *(float2*)&b[0] = *(const float2*)&Ws[k][c0];
            *(float2*)&b[2] = *(const float2*)&Ws[k][32 + c0];
            *(float2*)&b[4] = *(const float2*)&Ws[k][64 + c0];
#pragma unroll
            for (int i = 0; i < 4; ++i)
#pragma unroll
                for (int j = 0; j < 6; ++j)
                    acc[i][j] = fmaf(a[i], b[j], acc[i][j]);
        }
        __syncthreads();
    }

    // Fused GRU elementwise epilogue.
    const float bh0 = bhn[j0 + c0];
    const float bh1 = bhn[j0 + c0 + 1];
#pragma unroll
    for (int i = 0; i < 4; ++i) {
        const int b = b0 + r0 + i;
        const float m = (resets_t[b] != 0) ? 0.0f : 1.0f;
        const float* xg = Xg_t + (size_t)b * G3 + j0 + c0;
        const float hp0 = prev[(size_t)b * HH + j0 + c0 + 0] * m;
        const float hp1 = prev[(size_t)b * HH + j0 + c0 + 1] * m;

        float r0v = sigmoidf_(xg[0]        + acc[i][0]);
        float r1v = sigmoidf_(xg[1]        + acc[i][1]);
        float z0v = sigmoidf_(xg[512 + 0]  + acc[i][2]);
        float z1v = sigmoidf_(xg[512 + 1]  + acc[i][3]);
        float n0v = tanhf(xg[1024 + 0] + r0v * (acc[i][4] + bh0));
        float n1v = tanhf(xg[1024 + 1] + r1v * (acc[i][5] + bh1));

        float* orow = out_t + (size_t)b * HH + j0 + c0;
        orow[0] = (1.0f - z0v) * n0v + z0v * hp0;
        orow[1] = (1.0f - z1v) * n1v + z1v * hp1;
    }
}

// ----------------------------------------------------------------------------
// Launch: 1 input GEMM + 512 sequential step kernels. Graph-capturable
// (plain kernel launches only), allocation-free (scratch is a device global).
// Carry chain: step t reads out[t-1] (t=0 reads init_h) and writes out[t].
// ----------------------------------------------------------------------------
extern "C" void kernel_launch(void* const* d_in, const int* in_sizes, int n_in,
                              void* d_out, int out_size)
{
    const float* ins    = (const float*)d_in[0];
    const int*   resets = (const int*)d_in[1];   // bool -> int32 per harness dtypes
    const float* init_h = (const float*)d_in[2];
    const float* W_ir   = (const float*)d_in[3];
    const float* W_iz   = (const float*)d_in[4];
    const float* W_in   = (const float*)d_in[5];
    const float* b_ir   = (const float*)d_in[6];
    const float* b_iz   = (const float*)d_in[7];
    const float* b_in   = (const float*)d_in[8];
    const float* W_hr   = (const float*)d_in[9];
    const float* W_hz   = (const float*)d_in[10];
    const float* W_hn   = (const float*)d_in[11];
    const float* b_hn   = (const float*)d_in[12];
    float* out = (float*)d_out;

    // Phase 1: all input-side projections in one big GEMM.
    {
        dim3 grid((TT * BB) / 128, 12);
        input_gemm_kernel<<<grid, 256>>>(ins, W_ir, W_iz, W_in, b_ir, b_iz, b_in);
    }

    // Phase 2: sequential recurrence, one fused kernel per timestep.
    {
        dim3 grid(HH / 32, BB / 32);   // 16 x 8 = 128 CTAs
        for (int t = 0; t < TT; ++t) {
            const float* prev = (t == 0) ? init_h : (out + (size_t)(t - 1) * BB * HH);
            gru_step_kernel<<<grid, 128>>>(prev,
                                           resets + (size_t)t * BB,
                                           W_hr, W_hz, W_hn, b_hn,
                                           out + (size_t)t * BB * HH,
                                           t);
        }
    }
}

// round 5
// speedup vs baseline: 1.0006x; 1.0006x over previous
#include <cuda_runtime.h>
#include <cuda_bf16.h>
#include <cstdint>
#include <cmath>

// Problem dims (fixed by the reference).
#define TT 512
#define BB 256
#define HH 512
#define G3 1536
#define MTOT (TT*BB)   // 131072

// -------------------- device scratch (no cudaMalloc allowed) --------------------
__device__ float    g_Xg[(size_t)MTOT * G3];        // fp32 input-side preactivations
__device__ uint16_t g_Xh[(size_t)MTOT * HH];        // bf16 hi of ins
__device__ uint16_t g_Xl[(size_t)MTOT * HH];        // bf16 lo of ins
__device__ uint16_t g_Wt_hi[(size_t)G3 * HH];       // input weights, transposed [ncol][k]
__device__ uint16_t g_Wt_lo[(size_t)G3 * HH];
__device__ float    g_bias[G3];

// -------------------- helpers --------------------
__device__ __forceinline__ uint32_t smem_u32(const void* p) {
    uint32_t a;
    asm("{ .reg .u64 t; cvta.to.shared.u64 t, %1; cvt.u32.u64 %0, t; }" : "=r"(a) : "l"(p));
    return a;
}
__device__ __forceinline__ void ldm_x4(uint32_t* r, uint32_t addr) {
    asm volatile("ldmatrix.sync.aligned.m8n8.x4.shared.b16 {%0,%1,%2,%3}, [%4];"
                 : "=r"(r[0]), "=r"(r[1]), "=r"(r[2]), "=r"(r[3]) : "r"(addr));
}
__device__ __forceinline__ void ldm_x2(uint32_t* r, uint32_t addr) {
    asm volatile("ldmatrix.sync.aligned.m8n8.x2.shared.b16 {%0,%1}, [%2];"
                 : "=r"(r[0]), "=r"(r[1]) : "r"(addr));
}
// D(16x8,f32) += A(16x16 bf16 row) * B(16x8 bf16 col)
__device__ __forceinline__ void mma16816(float* c, const uint32_t* a, const uint32_t* b) {
    asm volatile("mma.sync.aligned.m16n8k16.row.col.f32.bf16.bf16.f32 "
                 "{%0,%1,%2,%3}, {%4,%5,%6,%7}, {%8,%9}, {%0,%1,%2,%3};"
                 : "+f"(c[0]), "+f"(c[1]), "+f"(c[2]), "+f"(c[3])
                 : "r"(a[0]), "r"(a[1]), "r"(a[2]), "r"(a[3]), "r"(b[0]), "r"(b[1]));
}
__device__ __forceinline__ void split2(float x, uint16_t& h, uint16_t& l) {
    __nv_bfloat16 hb = __float2bfloat16_rn(x);
    __nv_bfloat16 lb = __float2bfloat16_rn(x - __bfloat162float(hb));
    h = __bfloat16_as_ushort(hb);
    l = __bfloat16_as_ushort(lb);
}
__device__ __forceinline__ float sigmoidf_(float x) { return 1.0f / (1.0f + expf(-x)); }

// ----------------------------------------------------------------------------
// Prep 1: split ins fp32 -> bf16 hi/lo, row-major [MTOT][512].
// ----------------------------------------------------------------------------
__global__ __launch_bounds__(256) void prep_x_kernel(const float* __restrict__ X) {
    size_t u = (size_t)blockIdx.x * 256 + threadIdx.x;
    if (u >= (size_t)MTOT * HH / 8) return;
    size_t base = u * 8;
    float4 v0 = *(const float4*)(X + base);
    float4 v1 = *(const float4*)(X + base + 4);
    float xs[8] = {v0.x, v0.y, v0.z, v0.w, v1.x, v1.y, v1.z, v1.w};
    uint16_t hp[8], lp[8];
#pragma unroll
    for (int j = 0; j < 8; ++j) split2(xs[j], hp[j], lp[j]);
    *(uint4*)(g_Xh + base) = *(uint4*)hp;
    *(uint4*)(g_Xl + base) = *(uint4*)lp;
}

// ----------------------------------------------------------------------------
// Prep 2: transpose + split input weights: Wt[ncol][k] = W_gate[k][j],
// ncol = gate*512 + j. Also bias concat.
// ----------------------------------------------------------------------------
__global__ __launch_bounds__(256) void prep_w_kernel(
    const float* __restrict__ Wir, const float* __restrict__ Wiz, const float* __restrict__ Win,
    const float* __restrict__ bir, const float* __restrict__ biz, const float* __restrict__ bin) {
    int u = blockIdx.x * 256 + threadIdx.x;
    if (u >= G3 * HH / 8) return;
    int ncol = u >> 6;
    int k0 = (u & 63) * 8;
    int gate = ncol >> 9, j = ncol & 511;
    const float* Wi = (gate == 0) ? Wir : (gate == 1) ? Wiz : Win;
    uint16_t ih[8], il[8];
#pragma unroll
    for (int i = 0; i < 8; ++i)
        split2(Wi[(size_t)(k0 + i) * HH + j], ih[i], il[i]);
    size_t off = (size_t)ncol * HH + k0;
    *(uint4*)(g_Wt_hi + off) = *(uint4*)ih;
    *(uint4*)(g_Wt_lo + off) = *(uint4*)il;
    if ((u & 63) == 0) {
        const float* bias = (gate == 0) ? bir : (gate == 1) ? biz : bin;
        g_bias[ncol] = bias[j];
    }
}

// ----------------------------------------------------------------------------
// Input GEMM via mma.sync: Xg = split-bf16(X) @ split-bf16(Wcat) + bias.
// CTA 128M x 64N, 256 thr (8 warps as 4m x 2n), K chunks of 32, 3 terms.
// Grid (1024, 24).
// ----------------------------------------------------------------------------
__global__ __launch_bounds__(256) void input_gemm_mma() {
    __shared__ uint16_t Ah[128][40], Al[128][40], Bh[64][40], Bl[64][40];
    const int tid = threadIdx.x;
    const int w = tid >> 5, l = tid & 31;
    const int m0 = blockIdx.x * 128;
    const int n0 = blockIdx.y * 64;
    const int wm = w & 3, wn = w >> 2;

    float c[2][4][4];
#pragma unroll
    for (int mi = 0; mi < 2; ++mi)
#pragma unroll
        for (int ni = 0; ni < 4; ++ni)
#pragma unroll
            for (int q = 0; q < 4; ++q) c[mi][ni][q] = 0.0f;

    const int ar = tid >> 1, ah_half = tid & 1;
    const int br = tid >> 2, bq = tid & 3;

    for (int kt = 0; kt < HH; kt += 32) {
        {
            const uint4* sh = (const uint4*)(g_Xh + (size_t)(m0 + ar) * HH + kt + ah_half * 16);
            const uint4* sl = (const uint4*)(g_Xl + (size_t)(m0 + ar) * HH + kt + ah_half * 16);
            *(uint4*)&Ah[ar][ah_half * 16]     = sh[0];
            *(uint4*)&Ah[ar][ah_half * 16 + 8] = sh[1];
            *(uint4*)&Al[ar][ah_half * 16]     = sl[0];
            *(uint4*)&Al[ar][ah_half * 16 + 8] = sl[1];
            *(uint4*)&Bh[br][bq * 8] = *(const uint4*)(g_Wt_hi + (size_t)(n0 + br) * HH + kt + bq * 8);
            *(uint4*)&Bl[br][bq * 8] = *(const uint4*)(g_Wt_lo + (size_t)(n0 + br) * HH + kt + bq * 8);
        }
        __syncthreads();

#pragma unroll
        for (int kc = 0; kc < 32; kc += 16) {
            uint32_t afh[2][4], afl[2][4];
#pragma unroll
            for (int mi = 0; mi < 2; ++mi) {
                const int row = wm * 32 + mi * 16 + (l & 15);
                const int col = kc + (l >> 4) * 8;
                ldm_x4(afh[mi], smem_u32(&Ah[row][col]));
                ldm_x4(afl[mi], smem_u32(&Al[row][col]));
            }
#pragma unroll
            for (int ni = 0; ni < 4; ++ni) {
                const int nrow = wn * 32 + ni * 8 + (l & 7);
                const int ncolk = kc + ((l >> 3) & 1) * 8;
                uint32_t bfh[2], bfl[2];
                ldm_x2(bfh, smem_u32(&Bh[nrow][ncolk]));
                ldm_x2(bfl, smem_u32(&Bl[nrow][ncolk]));
#pragma unroll
                for (int mi = 0; mi < 2; ++mi) {
                    mma16816(c[mi][ni], afh[mi], bfh);
                    mma16816(c[mi][ni], afh[mi], bfl);
                    mma16816(c[mi][ni], afl[mi], bfh);
                }
            }
        }
        __syncthreads();
    }

    const int g = l >> 2, tq = l & 3;
#pragma unroll
    for (int mi = 0; mi < 2; ++mi)
#pragma unroll
        for (int ni = 0; ni < 4; ++ni) {
            const int ncol = n0 + wn * 32 + ni * 8 + tq * 2;
            const float2 bv = *(const float2*)&g_bias[ncol];
            const int row = m0 + wm * 32 + mi * 16 + g;
            float2 v0 = {c[mi][ni][0] + bv.x, c[mi][ni][1] + bv.y};
            float2 v1 = {c[mi][ni][2] + bv.x, c[mi][ni][3] + bv.y};
            *(float2*)&g_Xg[(size_t)row * G3 + ncol]       = v0;
            *(float2*)&g_Xg[(size_t)(row + 8) * G3 + ncol] = v1;
        }
}

// ----------------------------------------------------------------------------
// GRU step (fp32, KNOWN-GOOD math from R2, occupancy-fixed tiling):
// CTA tile 32 batch x (16 cols x 3 gates), grid (32, 8) = 256 CTAs x 128 thr
// -> ~2 CTAs/SM. Per-thread: 4 rows x 1 col per gate.
// ----------------------------------------------------------------------------
__global__ __launch_bounds__(128) void gru_step_kernel(
    const float* __restrict__ prev,
    const int* __restrict__ resets_t,
    const float* __restrict__ Whr, const float* __restrict__ Whz,
    const float* __restrict__ Whn, const float* __restrict__ bhn,
    float* __restrict__ out_t,
    int t)
{
    __shared__ float Hs[32][36];   // [k][row]
    __shared__ float Ws[32][48];   // [k][gate*16 + c]

    const int tid = threadIdx.x;
    const int j0  = blockIdx.x * 16;
    const int b0  = blockIdx.y * 32;
    const int tr  = tid & 7;
    const int tc  = tid >> 3;          // 0..15
    const int r0  = tr * 4;

    const float* __restrict__ Xg_t = g_Xg + (size_t)t * BB * G3;

    float acc[4][3];
#pragma unroll
    for (int i = 0; i < 4; ++i)
#pragma unroll
        for (int j = 0; j < 3; ++j) acc[i][j] = 0.0f;

    const int w_kk = tid >> 2;          // 0..31
    const int w_c4 = (tid & 3) * 4;     // 0..12

    for (int k0 = 0; k0 < HH; k0 += 32) {
#pragma unroll
        for (int q = 0; q < 2; ++q) {
            const int id = tid + q * 128;
            const int rr = id >> 3;
            const int kc = (id & 7) * 4;
            const float m = (resets_t[b0 + rr] != 0) ? 0.0f : 1.0f;
            float4 v = *(const float4*)(prev + (size_t)(b0 + rr) * HH + k0 + kc);
            Hs[kc + 0][rr] = v.x * m;
            Hs[kc + 1][rr] = v.y * m;
            Hs[kc + 2][rr] = v.z * m;
            Hs[kc + 3][rr] = v.w * m;
        }
        {
            const size_t off = (size_t)(k0 + w_kk) * HH + j0 + w_c4;
            *(float4*)&Ws[w_kk][ 0 + w_c4] = *(const float4*)(Whr + off);
            *(float4*)&Ws[w_kk][16 + w_c4] = *(const float4*)(Whz + off);
            *(float4*)&Ws[w_kk][32 + w_c4] = *(const float4*)(Whn + off);
        }
        __syncthreads();

#pragma unroll 8
        for (int k = 0; k < 32; ++k) {
            float a[4];
            *(float4*)&a[0] = *(const float4*)&Hs[k][r0];
            const float br_ = Ws[k][tc];
            const float bz_ = Ws[k][16 + tc];
            const float bn_ = Ws[k][32 + tc];
#pragma unroll
            for (int i = 0; i < 4; ++i) {
                acc[i][0] = fmaf(a[i], br_, acc[i][0]);
                acc[i][1] = fmaf(a[i], bz_, acc[i][1]);
                acc[i][2] = fmaf(a[i], bn_, acc[i][2]);
            }
        }
        __syncthreads();
    }

    const int j = j0 + tc;
    const float bh = bhn[j];
#pragma unroll
    for (int i = 0; i < 4; ++i) {
        const int b = b0 + r0 + i;
        const float m = (resets_t[b] != 0) ? 0.0f : 1.0f;
        const float hp = prev[(size_t)b * HH + j] * m;
        const float* xg = Xg_t + (size_t)b * G3 + j;
        float rv = sigmoidf_(xg[0]    + acc[i][0]);
        float zv = sigmoidf_(xg[512]  + acc[i][1]);
        float nv = tanhf(xg[1024] + rv * (acc[i][2] + bh));
        out_t[(size_t)b * HH + j] = (1.0f - zv) * nv + zv * hp;
    }
}

// ----------------------------------------------------------------------------
// Launch: 2 prep kernels + mma input GEMM + 512 fp32 step kernels.
// Graph-capturable, allocation-free.
// ----------------------------------------------------------------------------
extern "C" void kernel_launch(void* const* d_in, const int* in_sizes, int n_in,
                              void* d_out, int out_size)
{
    const float* ins    = (const float*)d_in[0];
    const int*   resets = (const int*)d_in[1];
    const float* init_h = (const float*)d_in[2];
    const float* W_ir   = (const float*)d_in[3];
    const float* W_iz   = (const float*)d_in[4];
    const float* W_in   = (const float*)d_in[5];
    const float* b_ir   = (const float*)d_in[6];
    const float* b_iz   = (const float*)d_in[7];
    const float* b_in   = (const float*)d_in[8];
    const float* W_hr   = (const float*)d_in[9];
    const float* W_hz   = (const float*)d_in[10];
    const float* W_hn   = (const float*)d_in[11];
    const float* b_hn   = (const float*)d_in[12];
    float* out = (float*)d_out;

    prep_x_kernel<<<(int)(((size_t)MTOT * HH / 8 + 255) / 256), 256>>>(ins);
    prep_w_kernel<<<(G3 * HH / 8 + 255) / 256, 256>>>(W_ir, W_iz, W_in, b_ir, b_iz, b_in);

    input_gemm_mma<<<dim3(MTOT / 128, G3 / 64), 256>>>();

    {
        dim3 grid(HH / 16, BB / 32);   // 32 x 8 = 256 CTAs
        for (int t = 0; t < TT; ++t) {
            const float* prev = (t == 0) ? init_h : (out + (size_t)(t - 1) * BB * HH);
            gru_step_kernel<<<grid, 128>>>(prev,
                                           resets + (size_t)t * BB,
                                           W_hr, W_hz, W_hn, b_hn,
                                           out + (size_t)t * BB * HH,
                                           t);
        }
    }
}

// round 6
// speedup vs baseline: 1.8256x; 1.8244x over previous
#include <cuda_runtime.h>
#include <cuda_bf16.h>
#include <cstdint>
#include <cmath>

// Problem dims (fixed by the reference).
#define TT 512
#define BB 256
#define HH 512
#define G3 1536
#define MTOT (TT*BB)   // 131072

// -------------------- device scratch (no cudaMalloc allowed) --------------------
__device__ float    g_Xg[(size_t)MTOT * G3];        // fp32 input-side preactivations
__device__ uint16_t g_Xh[(size_t)MTOT * HH];        // bf16 hi of ins
__device__ uint16_t g_Xl[(size_t)MTOT * HH];        // bf16 lo of ins
__device__ uint16_t g_Wt_hi[(size_t)G3 * HH];       // input weights, transposed [ncol][k]
__device__ uint16_t g_Wt_lo[(size_t)G3 * HH];
__device__ uint16_t g_Wht_hi[(size_t)G3 * HH];      // hidden weights, transposed [ncol][k]
__device__ uint16_t g_Wht_lo[(size_t)G3 * HH];
__device__ uint16_t g_Hh[2 * BB * HH];              // ping-pong split h (hi)
__device__ uint16_t g_Hl[2 * BB * HH];              // ping-pong split h (lo)
__device__ float    g_bias[G3];
__device__ unsigned int g_bar;                      // persistent-kernel grid barrier

// -------------------- helpers --------------------
__device__ __forceinline__ uint32_t smem_u32(const void* p) {
    uint32_t a;
    asm("{ .reg .u64 t; cvta.to.shared.u64 t, %1; cvt.u32.u64 %0, t; }" : "=r"(a) : "l"(p));
    return a;
}
__device__ __forceinline__ void ldm_x4(uint32_t* r, uint32_t addr) {
    asm volatile("ldmatrix.sync.aligned.m8n8.x4.shared.b16 {%0,%1,%2,%3}, [%4];"
                 : "=r"(r[0]), "=r"(r[1]), "=r"(r[2]), "=r"(r[3]) : "r"(addr));
}
__device__ __forceinline__ void ldm_x2(uint32_t* r, uint32_t addr) {
    asm volatile("ldmatrix.sync.aligned.m8n8.x2.shared.b16 {%0,%1}, [%2];"
                 : "=r"(r[0]), "=r"(r[1]) : "r"(addr));
}
// D(16x8,f32) += A(16x16 bf16 row) * B(16x8 bf16 col)
__device__ __forceinline__ void mma16816(float* c, const uint32_t* a, const uint32_t* b) {
    asm volatile("mma.sync.aligned.m16n8k16.row.col.f32.bf16.bf16.f32 "
                 "{%0,%1,%2,%3}, {%4,%5,%6,%7}, {%8,%9}, {%0,%1,%2,%3};"
                 : "+f"(c[0]), "+f"(c[1]), "+f"(c[2]), "+f"(c[3])
                 : "r"(a[0]), "r"(a[1]), "r"(a[2]), "r"(a[3]), "r"(b[0]), "r"(b[1]));
}
__device__ __forceinline__ void split2(float x, uint16_t& h, uint16_t& l) {
    __nv_bfloat16 hb = __float2bfloat16_rn(x);
    __nv_bfloat16 lb = __float2bfloat16_rn(x - __bfloat162float(hb));
    h = __bfloat16_as_ushort(hb);
    l = __bfloat16_as_ushort(lb);
}
__device__ __forceinline__ float sigmoidf_(float x) { return 1.0f / (1.0f + expf(-x)); }

// ----------------------------------------------------------------------------
// Prep 1: split ins fp32 -> bf16 hi/lo, row-major [MTOT][512].
// ----------------------------------------------------------------------------
__global__ __launch_bounds__(256) void prep_x_kernel(const float* __restrict__ X) {
    size_t u = (size_t)blockIdx.x * 256 + threadIdx.x;
    if (u >= (size_t)MTOT * HH / 8) return;
    size_t base = u * 8;
    float4 v0 = *(const float4*)(X + base);
    float4 v1 = *(const float4*)(X + base + 4);
    float xs[8] = {v0.x, v0.y, v0.z, v0.w, v1.x, v1.y, v1.z, v1.w};
    uint16_t hp[8], lp[8];
#pragma unroll
    for (int j = 0; j < 8; ++j) split2(xs[j], hp[j], lp[j]);
    *(uint4*)(g_Xh + base) = *(uint4*)hp;
    *(uint4*)(g_Xl + base) = *(uint4*)lp;
}

// ----------------------------------------------------------------------------
// Prep 2: transpose + split BOTH weight sets: Wt[ncol][k] = W_gate[k][j],
// ncol = gate*512 + j. Also bias concat.
// ----------------------------------------------------------------------------
__global__ __launch_bounds__(256) void prep_w_kernel(
    const float* __restrict__ Wir, const float* __restrict__ Wiz, const float* __restrict__ Win,
    const float* __restrict__ Whr, const float* __restrict__ Whz, const float* __restrict__ Whn,
    const float* __restrict__ bir, const float* __restrict__ biz, const float* __restrict__ bin) {
    int u = blockIdx.x * 256 + threadIdx.x;
    if (u >= G3 * HH / 8) return;
    int ncol = u >> 6;
    int k0 = (u & 63) * 8;
    int gate = ncol >> 9, j = ncol & 511;
    const float* Wi = (gate == 0) ? Wir : (gate == 1) ? Wiz : Win;
    const float* Wh = (gate == 0) ? Whr : (gate == 1) ? Whz : Whn;
    uint16_t ih[8], il[8], hh[8], hl[8];
#pragma unroll
    for (int i = 0; i < 8; ++i) {
        split2(Wi[(size_t)(k0 + i) * HH + j], ih[i], il[i]);
        split2(Wh[(size_t)(k0 + i) * HH + j], hh[i], hl[i]);
    }
    size_t off = (size_t)ncol * HH + k0;
    *(uint4*)(g_Wt_hi + off)  = *(uint4*)ih;
    *(uint4*)(g_Wt_lo + off)  = *(uint4*)il;
    *(uint4*)(g_Wht_hi + off) = *(uint4*)hh;
    *(uint4*)(g_Wht_lo + off) = *(uint4*)hl;
    if ((u & 63) == 0) {
        const float* bias = (gate == 0) ? bir : (gate == 1) ? biz : bin;
        g_bias[ncol] = bias[j];
    }
}

// ----------------------------------------------------------------------------
// Prep 3: split init_h into ping-pong buffer 0; reset the grid barrier.
// ----------------------------------------------------------------------------
__global__ __launch_bounds__(256) void prep_h_kernel(const float* __restrict__ H0) {
    int u = blockIdx.x * 256 + threadIdx.x;
    if (u == 0) g_bar = 0;
    if (u >= BB * HH / 8) return;
    size_t base = (size_t)u * 8;
    float4 v0 = *(const float4*)(H0 + base);
    float4 v1 = *(const float4*)(H0 + base + 4);
    float xs[8] = {v0.x, v0.y, v0.z, v0.w, v1.x, v1.y, v1.z, v1.w};
    uint16_t hp[8], lp[8];
#pragma unroll
    for (int j = 0; j < 8; ++j) split2(xs[j], hp[j], lp[j]);
    *(uint4*)(g_Hh + base) = *(uint4*)hp;
    *(uint4*)(g_Hl + base) = *(uint4*)lp;
}

// ----------------------------------------------------------------------------
// Input GEMM via mma.sync (UNCHANGED, proven correct in R5).
// CTA 128M x 64N, 256 thr (8 warps as 4m x 2n), K chunks of 32, 3 terms.
// ----------------------------------------------------------------------------
__global__ __launch_bounds__(256) void input_gemm_mma() {
    __shared__ uint16_t Ah[128][40], Al[128][40], Bh[64][40], Bl[64][40];
    const int tid = threadIdx.x;
    const int w = tid >> 5, l = tid & 31;
    const int m0 = blockIdx.x * 128;
    const int n0 = blockIdx.y * 64;
    const int wm = w & 3, wn = w >> 2;

    float c[2][4][4];
#pragma unroll
    for (int mi = 0; mi < 2; ++mi)
#pragma unroll
        for (int ni = 0; ni < 4; ++ni)
#pragma unroll
            for (int q = 0; q < 4; ++q) c[mi][ni][q] = 0.0f;

    const int ar = tid >> 1, ah_half = tid & 1;
    const int br = tid >> 2, bq = tid & 3;

    for (int kt = 0; kt < HH; kt += 32) {
        {
            const uint4* sh = (const uint4*)(g_Xh + (size_t)(m0 + ar) * HH + kt + ah_half * 16);
            const uint4* sl = (const uint4*)(g_Xl + (size_t)(m0 + ar) * HH + kt + ah_half * 16);
            *(uint4*)&Ah[ar][ah_half * 16]     = sh[0];
            *(uint4*)&Ah[ar][ah_half * 16 + 8] = sh[1];
            *(uint4*)&Al[ar][ah_half * 16]     = sl[0];
            *(uint4*)&Al[ar][ah_half * 16 + 8] = sl[1];
            *(uint4*)&Bh[br][bq * 8] = *(const uint4*)(g_Wt_hi + (size_t)(n0 + br) * HH + kt + bq * 8);
            *(uint4*)&Bl[br][bq * 8] = *(const uint4*)(g_Wt_lo + (size_t)(n0 + br) * HH + kt + bq * 8);
        }
        __syncthreads();

#pragma unroll
        for (int kc = 0; kc < 32; kc += 16) {
            uint32_t afh[2][4], afl[2][4];
#pragma unroll
            for (int mi = 0; mi < 2; ++mi) {
                const int row = wm * 32 + mi * 16 + (l & 15);
                const int col = kc + (l >> 4) * 8;
                ldm_x4(afh[mi], smem_u32(&Ah[row][col]));
                ldm_x4(afl[mi], smem_u32(&Al[row][col]));
            }
#pragma unroll
            for (int ni = 0; ni < 4; ++ni) {
                const int nrow = wn * 32 + ni * 8 + (l & 7);
                const int ncolk = kc + ((l >> 3) & 1) * 8;
                uint32_t bfh[2], bfl[2];
                ldm_x2(bfh, smem_u32(&Bh[nrow][ncolk]));
                ldm_x2(bfl, smem_u32(&Bl[nrow][ncolk]));
#pragma unroll
                for (int mi = 0; mi < 2; ++mi) {
                    mma16816(c[mi][ni], afh[mi], bfh);
                    mma16816(c[mi][ni], afh[mi], bfl);
                    mma16816(c[mi][ni], afl[mi], bfh);
                }
            }
        }
        __syncthreads();
    }

    const int g = l >> 2, tq = l & 3;
#pragma unroll
    for (int mi = 0; mi < 2; ++mi)
#pragma unroll
        for (int ni = 0; ni < 4; ++ni) {
            const int ncol = n0 + wn * 32 + ni * 8 + tq * 2;
            const float2 bv = *(const float2*)&g_bias[ncol];
            const int row = m0 + wm * 32 + mi * 16 + g;
            float2 v0 = {c[mi][ni][0] + bv.x, c[mi][ni][1] + bv.y};
            float2 v1 = {c[mi][ni][2] + bv.x, c[mi][ni][3] + bv.y};
            *(float2*)&g_Xg[(size_t)row * G3 + ncol]       = v0;
            *(float2*)&g_Xg[(size_t)(row + 8) * G3 + ncol] = v1;
        }
}

// ----------------------------------------------------------------------------
// Persistent GRU recurrence (R4 kernel + the one-line fix: B offset now
// includes the outer k-chunk `kt`, since W_h smem holds all 512 k-columns).
// Grid (64 j-tiles, 2 m-halves) = 128 CTAs, 256 thr = 8 warps.
// ----------------------------------------------------------------------------
#define SK_A_STRIDE 72
#define SK_W_STRIDE 520
#define SK_SMEM_BYTES ((2*128*SK_A_STRIDE + 2*24*SK_W_STRIDE) * 2)   // 86784

__global__ __launch_bounds__(256) void gru_persistent(
    const int* __restrict__ resets, const float* __restrict__ init_h,
    const float* __restrict__ bhn, float* __restrict__ out) {
    extern __shared__ __align__(16) uint16_t sm[];
    uint16_t* Ah = sm;
    uint16_t* Al = sm + 128 * SK_A_STRIDE;
    uint16_t* Wh = sm + 2 * 128 * SK_A_STRIDE;
    uint16_t* Wl = Wh + 24 * SK_W_STRIDE;

    const int tid = threadIdx.x;
    const int w = tid >> 5, l = tid & 31;
    const int j0 = blockIdx.x * 8;     // 0..504
    const int b0 = blockIdx.y * 128;   // 0 or 128
    const int g = l >> 2, tq = l & 3;

    // Load this CTA's W_h slices once: [gate][8 j][512 k].
    for (int u = tid; u < 24 * 64; u += 256) {
        const int row = u >> 6, q = u & 63;
        const int gate = row >> 3;
        const int ncol = gate * 512 + j0 + (row & 7);
        *(uint4*)&Wh[row * SK_W_STRIDE + q * 8] = *(const uint4*)(g_Wht_hi + (size_t)ncol * HH + q * 8);
        *(uint4*)&Wl[row * SK_W_STRIDE + q * 8] = *(const uint4*)(g_Wht_lo + (size_t)ncol * HH + q * 8);
    }
    __syncthreads();

    const int ar = tid >> 1, ahalf = tid & 1;   // A-copy mapping

    for (int t = 0; t < TT; ++t) {
        const int par = t & 1;
        const int* rst = resets + t * BB;
        const uint16_t* Hh = g_Hh + (size_t)par * BB * HH;
        const uint16_t* Hl = g_Hl + (size_t)par * BB * HH;

        float c[3][4];
#pragma unroll
        for (int gg = 0; gg < 3; ++gg)
#pragma unroll
            for (int q = 0; q < 4; ++q) c[gg][q] = 0.0f;

        for (int kt = 0; kt < HH; kt += 64) {
            {   // stage h tile (bf16 hi/lo) with per-row reset masking
                const int brow = b0 + ar;
                const bool rz = rst[brow] != 0;
                const uint4* sh = (const uint4*)(Hh + (size_t)brow * HH + kt + ahalf * 32);
                const uint4* sl = (const uint4*)(Hl + (size_t)brow * HH + kt + ahalf * 32);
                const uint4 z4 = {0u, 0u, 0u, 0u};
#pragma unroll
                for (int qq = 0; qq < 4; ++qq) {
                    *(uint4*)&Ah[ar * SK_A_STRIDE + ahalf * 32 + qq * 8] = rz ? z4 : sh[qq];
                    *(uint4*)&Al[ar * SK_A_STRIDE + ahalf * 32 + qq * 8] = rz ? z4 : sl[qq];
                }
            }
            __syncthreads();

#pragma unroll
            for (int kc = 0; kc < 64; kc += 16) {
                uint32_t afh[4], afl[4];
                const int arow = (16 * w + (l & 15)) * SK_A_STRIDE + kc + (l >> 4) * 8;
                ldm_x4(afh, smem_u32(&Ah[arow]));
                ldm_x4(afl, smem_u32(&Al[arow]));
#pragma unroll
                for (int gate = 0; gate < 3; ++gate) {
                    // FIX vs R4: include outer chunk offset `kt` (W_h smem spans all K).
                    const int boff = (gate * 8 + (l & 7)) * SK_W_STRIDE + kt + kc + ((l >> 3) & 1) * 8;
                    uint32_t bfh[2], bfl[2];
                    ldm_x2(bfh, smem_u32(&Wh[boff]));
                    ldm_x2(bfl, smem_u32(&Wl[boff]));
                    mma16816(c[gate], afh, bfh);
                    mma16816(c[gate], afh, bfl);
                    mma16816(c[gate], afl, bfh);
                }
            }
            __syncthreads();
        }

        // Fused GRU epilogue: each lane -> 2 rows x 2 cols.
        {
            const float* prevh = (t == 0) ? init_h : (out + (size_t)(t - 1) * BB * HH);
            float* outt = out + (size_t)t * BB * HH;
            const int C0 = j0 + tq * 2;
            const float2 bh2 = *(const float2*)&bhn[C0];
            const float* xgbase = g_Xg + (size_t)t * BB * G3;
            uint16_t* nHh = g_Hh + (size_t)(par ^ 1) * BB * HH;
            uint16_t* nHl = g_Hl + (size_t)(par ^ 1) * BB * HH;
#pragma unroll
            for (int rr = 0; rr < 2; ++rr) {
                const int row = b0 + 16 * w + g + rr * 8;
                const bool rz = rst[row] != 0;
                const float* xr = xgbase + (size_t)row * G3;
                const float2 xR = *(const float2*)&xr[C0];
                const float2 xZ = *(const float2*)&xr[512 + C0];
                const float2 xN = *(const float2*)&xr[1024 + C0];
                float2 hp = *(const float2*)&prevh[(size_t)row * HH + C0];
                if (rz) { hp.x = 0.0f; hp.y = 0.0f; }
                const float r0 = sigmoidf_(xR.x + c[0][rr * 2 + 0]);
                const float r1 = sigmoidf_(xR.y + c[0][rr * 2 + 1]);
                const float z0 = sigmoidf_(xZ.x + c[1][rr * 2 + 0]);
                const float z1 = sigmoidf_(xZ.y + c[1][rr * 2 + 1]);
                const float n0 = tanhf(xN.x + r0 * (c[2][rr * 2 + 0] + bh2.x));
                const float n1 = tanhf(xN.y + r1 * (c[2][rr * 2 + 1] + bh2.y));
                const float h0 = (1.0f - z0) * n0 + z0 * hp.x;
                const float h1 = (1.0f - z1) * n1 + z1 * hp.y;
                *(float2*)&outt[(size_t)row * HH + C0] = make_float2(h0, h1);
                uint16_t hh0, hl0, hh1, hl1;
                split2(h0, hh0, hl0);
                split2(h1, hh1, hl1);
                *(uint32_t*)&nHh[(size_t)row * HH + C0] = ((uint32_t)hh1 << 16) | hh0;
                *(uint32_t*)&nHl[(size_t)row * HH + C0] = ((uint32_t)hl1 << 16) | hl0;
            }
        }

        // Grid-wide barrier: release writes, arrive, spin on acquire.
        __threadfence();
        __syncthreads();
        if (tid == 0) {
            asm volatile("red.release.gpu.add.u32 [%0], %1;" :: "l"(&g_bar), "r"(1u) : "memory");
            const unsigned target = 128u * (unsigned)(t + 1);
            unsigned v;
            do {
                asm volatile("ld.acquire.gpu.u32 %0, [%1];" : "=r"(v) : "l"(&g_bar) : "memory");
                if (v >= target) break;
                __nanosleep(32);
            } while (true);
        }
        __syncthreads();
    }
}

// ----------------------------------------------------------------------------
// Launch: 3 prep kernels + mma input GEMM + ONE persistent recurrence kernel.
// Graph-capturable (kernel launches only), allocation-free.
// ----------------------------------------------------------------------------
extern "C" void kernel_launch(void* const* d_in, const int* in_sizes, int n_in,
                              void* d_out, int out_size)
{
    const float* ins    = (const float*)d_in[0];
    const int*   resets = (const int*)d_in[1];
    const float* init_h = (const float*)d_in[2];
    const float* W_ir   = (const float*)d_in[3];
    const float* W_iz   = (const float*)d_in[4];
    const float* W_in   = (const float*)d_in[5];
    const float* b_ir   = (const float*)d_in[6];
    const float* b_iz   = (const float*)d_in[7];
    const float* b_in   = (const float*)d_in[8];
    const float* W_hr   = (const float*)d_in[9];
    const float* W_hz   = (const float*)d_in[10];
    const float* W_hn   = (const float*)d_in[11];
    const float* b_hn   = (const float*)d_in[12];
    float* out = (float*)d_out;

    cudaFuncSetAttribute(gru_persistent,
                         cudaFuncAttributeMaxDynamicSharedMemorySize, SK_SMEM_BYTES);

    prep_x_kernel<<<(int)(((size_t)MTOT * HH / 8 + 255) / 256), 256>>>(ins);
    prep_w_kernel<<<(G3 * HH / 8 + 255) / 256, 256>>>(W_ir, W_iz, W_in,
                                                      W_hr, W_hz, W_hn,
                                                      b_ir, b_iz, b_in);
    prep_h_kernel<<<(BB * HH / 8 + 255) / 256, 256>>>(init_h);

    input_gemm_mma<<<dim3(MTOT / 128, G3 / 64), 256>>>();

    gru_persistent<<<dim3(64, 2), 256, SK_SMEM_BYTES>>>(resets, init_h, b_hn, out);
}

// round 7
// speedup vs baseline: 2.1256x; 1.1644x over previous
#include <cuda_runtime.h>
#include <cuda_bf16.h>
#include <cstdint>
#include <cmath>

// Problem dims (fixed by the reference).
#define TT 512
#define BB 256
#define HH 512
#define G3 1536
#define MTOT (TT*BB)   // 131072

// -------------------- device scratch (no cudaMalloc allowed) --------------------
__device__ float    g_Xg[(size_t)MTOT * G3];        // fp32 input-side preactivations
__device__ uint16_t g_Xh[(size_t)MTOT * HH];        // bf16 hi of ins
__device__ uint16_t g_Xl[(size_t)MTOT * HH];        // bf16 lo of ins
__device__ uint16_t g_Wt_hi[(size_t)G3 * HH];       // input weights, transposed [ncol][k]
__device__ uint16_t g_Wt_lo[(size_t)G3 * HH];
__device__ uint16_t g_Wht_hi[(size_t)G3 * HH];      // hidden weights, transposed [ncol][k]
__device__ uint16_t g_Wht_lo[(size_t)G3 * HH];
__device__ uint16_t g_Hh[2 * BB * HH];              // ping-pong split h (hi)
__device__ uint16_t g_Hl[2 * BB * HH];              // ping-pong split h (lo)
__device__ float    g_Hf[2 * BB * HH];              // ping-pong fp32 h (L2-resident)
__device__ float    g_bias[G3];
__device__ unsigned int g_bar;                      // persistent-kernel grid barrier

// -------------------- helpers --------------------
__device__ __forceinline__ uint32_t smem_u32(const void* p) {
    uint32_t a;
    asm("{ .reg .u64 t; cvta.to.shared.u64 t, %1; cvt.u32.u64 %0, t; }" : "=r"(a) : "l"(p));
    return a;
}
__device__ __forceinline__ void ldm_x4(uint32_t* r, uint32_t addr) {
    asm volatile("ldmatrix.sync.aligned.m8n8.x4.shared.b16 {%0,%1,%2,%3}, [%4];"
                 : "=r"(r[0]), "=r"(r[1]), "=r"(r[2]), "=r"(r[3]) : "r"(addr));
}
__device__ __forceinline__ void ldm_x2(uint32_t* r, uint32_t addr) {
    asm volatile("ldmatrix.sync.aligned.m8n8.x2.shared.b16 {%0,%1}, [%2];"
                 : "=r"(r[0]), "=r"(r[1]) : "r"(addr));
}
// D(16x8,f32) += A(16x16 bf16 row) * B(16x8 bf16 col)
__device__ __forceinline__ void mma16816(float* c, const uint32_t* a, const uint32_t* b) {
    asm volatile("mma.sync.aligned.m16n8k16.row.col.f32.bf16.bf16.f32 "
                 "{%0,%1,%2,%3}, {%4,%5,%6,%7}, {%8,%9}, {%0,%1,%2,%3};"
                 : "+f"(c[0]), "+f"(c[1]), "+f"(c[2]), "+f"(c[3])
                 : "r"(a[0]), "r"(a[1]), "r"(a[2]), "r"(a[3]), "r"(b[0]), "r"(b[1]));
}
__device__ __forceinline__ void split2(float x, uint16_t& h, uint16_t& l) {
    __nv_bfloat16 hb = __float2bfloat16_rn(x);
    __nv_bfloat16 lb = __float2bfloat16_rn(x - __bfloat162float(hb));
    h = __bfloat16_as_ushort(hb);
    l = __bfloat16_as_ushort(lb);
}
__device__ __forceinline__ float sigmoidf_(float x) { return 1.0f / (1.0f + expf(-x)); }

// ----------------------------------------------------------------------------
// Prep 1: split ins fp32 -> bf16 hi/lo, row-major [MTOT][512].
// ----------------------------------------------------------------------------
__global__ __launch_bounds__(256) void prep_x_kernel(const float* __restrict__ X) {
    size_t u = (size_t)blockIdx.x * 256 + threadIdx.x;
    if (u >= (size_t)MTOT * HH / 8) return;
    size_t base = u * 8;
    float4 v0 = *(const float4*)(X + base);
    float4 v1 = *(const float4*)(X + base + 4);
    float xs[8] = {v0.x, v0.y, v0.z, v0.w, v1.x, v1.y, v1.z, v1.w};
    uint16_t hp[8], lp[8];
#pragma unroll
    for (int j = 0; j < 8; ++j) split2(xs[j], hp[j], lp[j]);
    *(uint4*)(g_Xh + base) = *(uint4*)hp;
    *(uint4*)(g_Xl + base) = *(uint4*)lp;
}

// ----------------------------------------------------------------------------
// Prep 2: transpose + split BOTH weight sets: Wt[ncol][k] = W_gate[k][j].
// ----------------------------------------------------------------------------
__global__ __launch_bounds__(256) void prep_w_kernel(
    const float* __restrict__ Wir, const float* __restrict__ Wiz, const float* __restrict__ Win,
    const float* __restrict__ Whr, const float* __restrict__ Whz, const float* __restrict__ Whn,
    const float* __restrict__ bir, const float* __restrict__ biz, const float* __restrict__ bin) {
    int u = blockIdx.x * 256 + threadIdx.x;
    if (u >= G3 * HH / 8) return;
    int ncol = u >> 6;
    int k0 = (u & 63) * 8;
    int gate = ncol >> 9, j = ncol & 511;
    const float* Wi = (gate == 0) ? Wir : (gate == 1) ? Wiz : Win;
    const float* Wh = (gate == 0) ? Whr : (gate == 1) ? Whz : Whn;
    uint16_t ih[8], il[8], hh[8], hl[8];
#pragma unroll
    for (int i = 0; i < 8; ++i) {
        split2(Wi[(size_t)(k0 + i) * HH + j], ih[i], il[i]);
        split2(Wh[(size_t)(k0 + i) * HH + j], hh[i], hl[i]);
    }
    size_t off = (size_t)ncol * HH + k0;
    *(uint4*)(g_Wt_hi + off)  = *(uint4*)ih;
    *(uint4*)(g_Wt_lo + off)  = *(uint4*)il;
    *(uint4*)(g_Wht_hi + off) = *(uint4*)hh;
    *(uint4*)(g_Wht_lo + off) = *(uint4*)hl;
    if ((u & 63) == 0) {
        const float* bias = (gate == 0) ? bir : (gate == 1) ? biz : bin;
        g_bias[ncol] = bias[j];
    }
}

// ----------------------------------------------------------------------------
// Prep 3: split init_h into ping-pong buffer 0 (bf16 hi/lo + fp32); reset barrier.
// ----------------------------------------------------------------------------
__global__ __launch_bounds__(256) void prep_h_kernel(const float* __restrict__ H0) {
    int u = blockIdx.x * 256 + threadIdx.x;
    if (u == 0) g_bar = 0;
    if (u >= BB * HH / 8) return;
    size_t base = (size_t)u * 8;
    float4 v0 = *(const float4*)(H0 + base);
    float4 v1 = *(const float4*)(H0 + base + 4);
    float xs[8] = {v0.x, v0.y, v0.z, v0.w, v1.x, v1.y, v1.z, v1.w};
    uint16_t hp[8], lp[8];
#pragma unroll
    for (int j = 0; j < 8; ++j) split2(xs[j], hp[j], lp[j]);
    *(uint4*)(g_Hh + base) = *(uint4*)hp;
    *(uint4*)(g_Hl + base) = *(uint4*)lp;
    *(float4*)(g_Hf + base)     = v0;
    *(float4*)(g_Hf + base + 4) = v1;
}

// ----------------------------------------------------------------------------
// Input GEMM via mma.sync (fragment math proven in R5/R6), now:
//  - grid (24 n-slabs, 1024 m-tiles), n fastest -> each A-tile DRAM-read once
//  - double-buffered smem, 1 syncthreads per 32-k chunk, LDG hidden under MMA
// CTA 128M x 64N, 256 thr (8 warps as 4m x 2n), 3 precision terms.
// ----------------------------------------------------------------------------
#define IG_ABUF (128*40)
#define IG_BBUF (64*40)
#define IG_SMEM_BYTES ((2*(2*IG_ABUF + 2*IG_BBUF)) * 2)   // 61440

__global__ __launch_bounds__(256) void input_gemm_mma() {
    extern __shared__ __align__(16) uint16_t ig_sm[];
    uint16_t* Abufh[2]; uint16_t* Abufl[2]; uint16_t* Bbufh[2]; uint16_t* Bbufl[2];
    {
        uint16_t* p = ig_sm;
        Abufh[0] = p; p += IG_ABUF;  Abufl[0] = p; p += IG_ABUF;
        Bbufh[0] = p; p += IG_BBUF;  Bbufl[0] = p; p += IG_BBUF;
        Abufh[1] = p; p += IG_ABUF;  Abufl[1] = p; p += IG_ABUF;
        Bbufh[1] = p; p += IG_BBUF;  Bbufl[1] = p;
    }
    const int tid = threadIdx.x;
    const int w = tid >> 5, l = tid & 31;
    const int n0 = blockIdx.x * 64;     // n fastest for L2 A-reuse
    const int m0 = blockIdx.y * 128;
    const int wm = w & 3, wn = w >> 2;

    float c[2][4][4];
#pragma unroll
    for (int mi = 0; mi < 2; ++mi)
#pragma unroll
        for (int ni = 0; ni < 4; ++ni)
#pragma unroll
            for (int q = 0; q < 4; ++q) c[mi][ni][q] = 0.0f;

    const int ar = tid >> 1, ah_half = tid & 1;
    const int br = tid >> 2, bq = tid & 3;

    uint4 sA[4], sB[2];
#define IG_LDG(kt) {                                                                   \
    const uint16_t* ph = g_Xh + (size_t)(m0 + ar) * HH + (kt) + ah_half * 16;          \
    const uint16_t* pl = g_Xl + (size_t)(m0 + ar) * HH + (kt) + ah_half * 16;          \
    sA[0] = *(const uint4*)ph;        sA[1] = *(const uint4*)(ph + 8);                 \
    sA[2] = *(const uint4*)pl;        sA[3] = *(const uint4*)(pl + 8);                 \
    sB[0] = *(const uint4*)(g_Wt_hi + (size_t)(n0 + br) * HH + (kt) + bq * 8);         \
    sB[1] = *(const uint4*)(g_Wt_lo + (size_t)(n0 + br) * HH + (kt) + bq * 8); }

    IG_LDG(0);
    for (int cb = 0; cb < 16; ++cb) {
        uint16_t* Ah = Abufh[cb & 1]; uint16_t* Al = Abufl[cb & 1];
        uint16_t* Bh = Bbufh[cb & 1]; uint16_t* Bl = Bbufl[cb & 1];
        // STS current chunk
        *(uint4*)&Ah[ar * 40 + ah_half * 16]     = sA[0];
        *(uint4*)&Ah[ar * 40 + ah_half * 16 + 8] = sA[1];
        *(uint4*)&Al[ar * 40 + ah_half * 16]     = sA[2];
        *(uint4*)&Al[ar * 40 + ah_half * 16 + 8] = sA[3];
        *(uint4*)&Bh[br * 40 + bq * 8] = sB[0];
        *(uint4*)&Bl[br * 40 + bq * 8] = sB[1];
        __syncthreads();
        if (cb < 15) IG_LDG((cb + 1) * 32);

#pragma unroll
        for (int kc = 0; kc < 32; kc += 16) {
            uint32_t afh[2][4], afl[2][4];
#pragma unroll
            for (int mi = 0; mi < 2; ++mi) {
                const int row = wm * 32 + mi * 16 + (l & 15);
                const int col = kc + (l >> 4) * 8;
                ldm_x4(afh[mi], smem_u32(&Ah[row * 40 + col]));
                ldm_x4(afl[mi], smem_u32(&Al[row * 40 + col]));
            }
#pragma unroll
            for (int ni = 0; ni < 4; ++ni) {
                const int nrow = wn * 32 + ni * 8 + (l & 7);
                const int ncolk = kc + ((l >> 3) & 1) * 8;
                uint32_t bfh[2], bfl[2];
                ldm_x2(bfh, smem_u32(&Bh[nrow * 40 + ncolk]));
                ldm_x2(bfl, smem_u32(&Bl[nrow * 40 + ncolk]));
#pragma unroll
                for (int mi = 0; mi < 2; ++mi) {
                    mma16816(c[mi][ni], afh[mi], bfh);
                    mma16816(c[mi][ni], afh[mi], bfl);
                    mma16816(c[mi][ni], afl[mi], bfh);
                }
            }
        }
    }
#undef IG_LDG

    const int g = l >> 2, tq = l & 3;
#pragma unroll
    for (int mi = 0; mi < 2; ++mi)
#pragma unroll
        for (int ni = 0; ni < 4; ++ni) {
            const int ncol = n0 + wn * 32 + ni * 8 + tq * 2;
            const float2 bv = *(const float2*)&g_bias[ncol];
            const int row = m0 + wm * 32 + mi * 16 + g;
            float2 v0 = {c[mi][ni][0] + bv.x, c[mi][ni][1] + bv.y};
            float2 v1 = {c[mi][ni][2] + bv.x, c[mi][ni][3] + bv.y};
            *(float2*)&g_Xg[(size_t)row * G3 + ncol]       = v0;
            *(float2*)&g_Xg[(size_t)(row + 8) * G3 + ncol] = v1;
        }
}

// ----------------------------------------------------------------------------
// Persistent GRU recurrence (proven R6 math), now software-pipelined:
//  - double-buffered A staging, 1 syncthreads per 64-k chunk (was 2)
//  - LDG(next chunk) issued before MMA(current) -> L2 latency hidden
//  - fp32 h ping-pong g_Hf (L2) replaces `out` DRAM reads in the epilogue
//  - Xg / h / reset operands prefetched at step start
// Grid (64 j-tiles, 2 m-halves) = 128 CTAs, 256 thr = 8 warps.
// ----------------------------------------------------------------------------
#define SK_A_STRIDE 72
#define SK_W_STRIDE 520
#define SK_ABUF (128 * SK_A_STRIDE)
#define SK_SMEM_BYTES ((4*SK_ABUF + 2*24*SK_W_STRIDE) * 2)   // 123648

__global__ __launch_bounds__(256) void gru_persistent(
    const int* __restrict__ resets, const float* __restrict__ bhn,
    float* __restrict__ out) {
    extern __shared__ __align__(16) uint16_t sm[];
    uint16_t* AbH[2]; uint16_t* AbL[2];
    AbH[0] = sm;               AbL[0] = sm + SK_ABUF;
    AbH[1] = sm + 2 * SK_ABUF; AbL[1] = sm + 3 * SK_ABUF;
    uint16_t* Wh = sm + 4 * SK_ABUF;
    uint16_t* Wl = Wh + 24 * SK_W_STRIDE;

    const int tid = threadIdx.x;
    const int w = tid >> 5, l = tid & 31;
    const int j0 = blockIdx.x * 8;     // 0..504
    const int b0 = blockIdx.y * 128;   // 0 or 128
    const int g = l >> 2, tq = l & 3;

    // Load this CTA's W_h slices once: [gate][8 j][512 k].
    for (int u = tid; u < 24 * 64; u += 256) {
        const int row = u >> 6, q = u & 63;
        const int gate = row >> 3;
        const int ncol = gate * 512 + j0 + (row & 7);
        *(uint4*)&Wh[row * SK_W_STRIDE + q * 8] = *(const uint4*)(g_Wht_hi + (size_t)ncol * HH + q * 8);
        *(uint4*)&Wl[row * SK_W_STRIDE + q * 8] = *(const uint4*)(g_Wht_lo + (size_t)ncol * HH + q * 8);
    }
    __syncthreads();

    const int ar = tid >> 1, ahalf = tid & 1;   // A staging: 2 thr/row, 32 k each

    for (int t = 0; t < TT; ++t) {
        const int par = t & 1;
        const int* rst = resets + t * BB;
        const uint16_t* Hh = g_Hh + (size_t)par * BB * HH;
        const uint16_t* Hl = g_Hl + (size_t)par * BB * HH;
        const float* prevh = g_Hf + (size_t)par * BB * HH;

        // --- prefetch epilogue operands (consumed ~5us later; latency hidden) ---
        float2 pxR[2], pxZ[2], pxN[2], php[2];
        bool rzrow[2];
        {
            const float* xgbase = g_Xg + (size_t)t * BB * G3;
            const int C0 = j0 + tq * 2;
#pragma unroll
            for (int rr = 0; rr < 2; ++rr) {
                const int row = b0 + 16 * w + g + rr * 8;
                rzrow[rr] = rst[row] != 0;
                const float* xr = xgbase + (size_t)row * G3;
                pxR[rr] = *(const float2*)&xr[C0];
                pxZ[rr] = *(const float2*)&xr[512 + C0];
                pxN[rr] = *(const float2*)&xr[1024 + C0];
                php[rr] = *(const float2*)&prevh[(size_t)row * HH + C0];
            }
        }

        const bool rz_stage = rst[b0 + ar] != 0;   // same rows every chunk

        float c[3][4];
#pragma unroll
        for (int gg = 0; gg < 3; ++gg)
#pragma unroll
            for (int q = 0; q < 4; ++q) c[gg][q] = 0.0f;

        uint4 rh[4], rl[4];
#define SK_LDG(kt) {                                                               \
    const uint4* sh = (const uint4*)(Hh + (size_t)(b0 + ar) * HH + (kt) + ahalf * 32); \
    const uint4* sl = (const uint4*)(Hl + (size_t)(b0 + ar) * HH + (kt) + ahalf * 32); \
    const uint4 z4 = {0u, 0u, 0u, 0u};                                             \
    rh[0] = rz_stage ? z4 : sh[0]; rh[1] = rz_stage ? z4 : sh[1];                  \
    rh[2] = rz_stage ? z4 : sh[2]; rh[3] = rz_stage ? z4 : sh[3];                  \
    rl[0] = rz_stage ? z4 : sl[0]; rl[1] = rz_stage ? z4 : sl[1];                  \
    rl[2] = rz_stage ? z4 : sl[2]; rl[3] = rz_stage ? z4 : sl[3]; }

        SK_LDG(0);
        for (int cb = 0; cb < 8; ++cb) {
            uint16_t* Ah = AbH[cb & 1];
            uint16_t* Al = AbL[cb & 1];
#pragma unroll
            for (int qq = 0; qq < 4; ++qq) {
                *(uint4*)&Ah[ar * SK_A_STRIDE + ahalf * 32 + qq * 8] = rh[qq];
                *(uint4*)&Al[ar * SK_A_STRIDE + ahalf * 32 + qq * 8] = rl[qq];
            }
            __syncthreads();
            if (cb < 7) SK_LDG((cb + 1) * 64);

#pragma unroll
            for (int kc = 0; kc < 64; kc += 16) {
                uint32_t afh[4], afl[4];
                const int arow = (16 * w + (l & 15)) * SK_A_STRIDE + kc + (l >> 4) * 8;
                ldm_x4(afh, smem_u32(&Ah[arow]));
                ldm_x4(afl, smem_u32(&Al[arow]));
#pragma unroll
                for (int gate = 0; gate < 3; ++gate) {
                    const int boff = (gate * 8 + (l & 7)) * SK_W_STRIDE + cb * 64 + kc + ((l >> 3) & 1) * 8;
                    uint32_t bfh[2], bfl[2];
                    ldm_x2(bfh, smem_u32(&Wh[boff]));
                    ldm_x2(bfl, smem_u32(&Wl[boff]));
                    mma16816(c[gate], afh, bfh);
                    mma16816(c[gate], afh, bfl);
                    mma16816(c[gate], afl, bfh);
                }
            }
        }
#undef SK_LDG

        // Fused GRU epilogue: each lane -> 2 rows x 2 cols.
        {
            float* outt = out + (size_t)t * BB * HH;
            const int C0 = j0 + tq * 2;
            const float2 bh2 = *(const float2*)&bhn[C0];
            uint16_t* nHh = g_Hh + (size_t)(par ^ 1) * BB * HH;
            uint16_t* nHl = g_Hl + (size_t)(par ^ 1) * BB * HH;
            float*    nHf = g_Hf + (size_t)(par ^ 1) * BB * HH;
#pragma unroll
            for (int rr = 0; rr < 2; ++rr) {
                const int row = b0 + 16 * w + g + rr * 8;
                float2 hp = php[rr];
                if (rzrow[rr]) { hp.x = 0.0f; hp.y = 0.0f; }
                const float r0 = sigmoidf_(pxR[rr].x + c[0][rr * 2 + 0]);
                const float r1 = sigmoidf_(pxR[rr].y + c[0][rr * 2 + 1]);
                const float z0 = sigmoidf_(pxZ[rr].x + c[1][rr * 2 + 0]);
                const float z1 = sigmoidf_(pxZ[rr].y + c[1][rr * 2 + 1]);
                const float n0 = tanhf(pxN[rr].x + r0 * (c[2][rr * 2 + 0] + bh2.x));
                const float n1 = tanhf(pxN[rr].y + r1 * (c[2][rr * 2 + 1] + bh2.y));
                const float h0 = (1.0f - z0) * n0 + z0 * hp.x;
                const float h1 = (1.0f - z1) * n1 + z1 * hp.y;
                *(float2*)&outt[(size_t)row * HH + C0] = make_float2(h0, h1);
                *(float2*)&nHf[(size_t)row * HH + C0]  = make_float2(h0, h1);
                uint16_t hh0, hl0, hh1, hl1;
                split2(h0, hh0, hl0);
                split2(h1, hh1, hl1);
                *(uint32_t*)&nHh[(size_t)row * HH + C0] = ((uint32_t)hh1 << 16) | hh0;
                *(uint32_t*)&nHl[(size_t)row * HH + C0] = ((uint32_t)hl1 << 16) | hl0;
            }
        }

        // Grid-wide barrier: release writes, arrive, spin on acquire.
        __threadfence();
        __syncthreads();
        if (tid == 0) {
            asm volatile("red.release.gpu.add.u32 [%0], %1;" :: "l"(&g_bar), "r"(1u) : "memory");
            const unsigned target = 128u * (unsigned)(t + 1);
            unsigned v;
            do {
                asm volatile("ld.acquire.gpu.u32 %0, [%1];" : "=r"(v) : "l"(&g_bar) : "memory");
                if (v >= target) break;
                __nanosleep(32);
            } while (true);
        }
        __syncthreads();
    }
}

// ----------------------------------------------------------------------------
// Launch: 3 prep kernels + mma input GEMM + ONE persistent recurrence kernel.
// Graph-capturable (kernel launches only), allocation-free.
// ----------------------------------------------------------------------------
extern "C" void kernel_launch(void* const* d_in, const int* in_sizes, int n_in,
                              void* d_out, int out_size)
{
    const float* ins    = (const float*)d_in[0];
    const int*   resets = (const int*)d_in[1];
    const float* init_h = (const float*)d_in[2];
    const float* W_ir   = (const float*)d_in[3];
    const float* W_iz   = (const float*)d_in[4];
    const float* W_in   = (const float*)d_in[5];
    const float* b_ir   = (const float*)d_in[6];
    const float* b_iz   = (const float*)d_in[7];
    const float* b_in   = (const float*)d_in[8];
    const float* W_hr   = (const float*)d_in[9];
    const float* W_hz   = (const float*)d_in[10];
    const float* W_hn   = (const float*)d_in[11];
    const float* b_hn   = (const float*)d_in[12];
    float* out = (float*)d_out;

    cudaFuncSetAttribute(input_gemm_mma,
                         cudaFuncAttributeMaxDynamicSharedMemorySize, IG_SMEM_BYTES);
    cudaFuncSetAttribute(gru_persistent,
                         cudaFuncAttributeMaxDynamicSharedMemorySize, SK_SMEM_BYTES);

    prep_x_kernel<<<(int)(((size_t)MTOT * HH / 8 + 255) / 256), 256>>>(ins);
    prep_w_kernel<<<(G3 * HH / 8 + 255) / 256, 256>>>(W_ir, W_iz, W_in,
                                                      W_hr, W_hz, W_hn,
                                                      b_ir, b_iz, b_in);
    prep_h_kernel<<<(BB * HH / 8 + 255) / 256, 256>>>(init_h);

    // n-slab fastest: each A m-tile is DRAM-read once, L2-served to 24 n-CTAs.
    input_gemm_mma<<<dim3(G3 / 64, MTOT / 128), 256, IG_SMEM_BYTES>>>();

    gru_persistent<<<dim3(64, 2), 256, SK_SMEM_BYTES>>>(resets, b_hn, out);
}

// round 8
// speedup vs baseline: 2.3125x; 1.0879x over previous
#include <cuda_runtime.h>
#include <cuda_bf16.h>
#include <cstdint>
#include <cmath>

// Problem dims (fixed by the reference).
#define TT 512
#define BB 256
#define HH 512
#define G3 1536
#define MTOT (TT*BB)   // 131072

// -------------------- device scratch (no cudaMalloc allowed) --------------------
__device__ float    g_Xg[(size_t)MTOT * G3];        // fp32 input-side preactivations
__device__ uint16_t g_Xh[(size_t)MTOT * HH];        // bf16 hi of ins
__device__ uint16_t g_Xl[(size_t)MTOT * HH];        // bf16 lo of ins
__device__ uint16_t g_Wt_hi[(size_t)G3 * HH];       // input weights, transposed [ncol][k]
__device__ uint16_t g_Wt_lo[(size_t)G3 * HH];
__device__ uint16_t g_Wht_hi[(size_t)G3 * HH];      // hidden weights, transposed [ncol][k]
__device__ uint16_t g_Wht_lo[(size_t)G3 * HH];
__device__ uint16_t g_Hh[2 * BB * HH];              // ping-pong split h (hi)
__device__ uint16_t g_Hl[2 * BB * HH];              // ping-pong split h (lo)
__device__ float    g_bias[G3];
__device__ unsigned int g_bar;                      // persistent-kernel grid barrier

// -------------------- helpers --------------------
__device__ __forceinline__ uint32_t smem_u32(const void* p) {
    uint32_t a;
    asm("{ .reg .u64 t; cvta.to.shared.u64 t, %1; cvt.u32.u64 %0, t; }" : "=r"(a) : "l"(p));
    return a;
}
__device__ __forceinline__ void ldm_x4(uint32_t* r, uint32_t addr) {
    asm volatile("ldmatrix.sync.aligned.m8n8.x4.shared.b16 {%0,%1,%2,%3}, [%4];"
                 : "=r"(r[0]), "=r"(r[1]), "=r"(r[2]), "=r"(r[3]) : "r"(addr));
}
__device__ __forceinline__ void ldm_x2(uint32_t* r, uint32_t addr) {
    asm volatile("ldmatrix.sync.aligned.m8n8.x2.shared.b16 {%0,%1}, [%2];"
                 : "=r"(r[0]), "=r"(r[1]) : "r"(addr));
}
// D(16x8,f32) += A(16x16 bf16 row) * B(16x8 bf16 col)
__device__ __forceinline__ void mma16816(float* c, const uint32_t* a, const uint32_t* b) {
    asm volatile("mma.sync.aligned.m16n8k16.row.col.f32.bf16.bf16.f32 "
                 "{%0,%1,%2,%3}, {%4,%5,%6,%7}, {%8,%9}, {%0,%1,%2,%3};"
                 : "+f"(c[0]), "+f"(c[1]), "+f"(c[2]), "+f"(c[3])
                 : "r"(a[0]), "r"(a[1]), "r"(a[2]), "r"(a[3]), "r"(b[0]), "r"(b[1]));
}
__device__ __forceinline__ void split2(float x, uint16_t& h, uint16_t& l) {
    __nv_bfloat16 hb = __float2bfloat16_rn(x);
    __nv_bfloat16 lb = __float2bfloat16_rn(x - __bfloat162float(hb));
    h = __bfloat16_as_ushort(hb);
    l = __bfloat16_as_ushort(lb);
}
__device__ __forceinline__ float sigmoidf_(float x) { return 1.0f / (1.0f + expf(-x)); }

// ----------------------------------------------------------------------------
// Prep 1: split ins fp32 -> bf16 hi/lo, row-major [MTOT][512].
// ----------------------------------------------------------------------------
__global__ __launch_bounds__(256) void prep_x_kernel(const float* __restrict__ X) {
    size_t u = (size_t)blockIdx.x * 256 + threadIdx.x;
    if (u >= (size_t)MTOT * HH / 8) return;
    size_t base = u * 8;
    float4 v0 = *(const float4*)(X + base);
    float4 v1 = *(const float4*)(X + base + 4);
    float xs[8] = {v0.x, v0.y, v0.z, v0.w, v1.x, v1.y, v1.z, v1.w};
    uint16_t hp[8], lp[8];
#pragma unroll
    for (int j = 0; j < 8; ++j) split2(xs[j], hp[j], lp[j]);
    *(uint4*)(g_Xh + base) = *(uint4*)hp;
    *(uint4*)(g_Xl + base) = *(uint4*)lp;
}

// ----------------------------------------------------------------------------
// Prep 2: transpose + split BOTH weight sets: Wt[ncol][k] = W_gate[k][j].
// ----------------------------------------------------------------------------
__global__ __launch_bounds__(256) void prep_w_kernel(
    const float* __restrict__ Wir, const float* __restrict__ Wiz, const float* __restrict__ Win,
    const float* __restrict__ Whr, const float* __restrict__ Whz, const float* __restrict__ Whn,
    const float* __restrict__ bir, const float* __restrict__ biz, const float* __restrict__ bin) {
    int u = blockIdx.x * 256 + threadIdx.x;
    if (u >= G3 * HH / 8) return;
    int ncol = u >> 6;
    int k0 = (u & 63) * 8;
    int gate = ncol >> 9, j = ncol & 511;
    const float* Wi = (gate == 0) ? Wir : (gate == 1) ? Wiz : Win;
    const float* Wh = (gate == 0) ? Whr : (gate == 1) ? Whz : Whn;
    uint16_t ih[8], il[8], hh[8], hl[8];
#pragma unroll
    for (int i = 0; i < 8; ++i) {
        split2(Wi[(size_t)(k0 + i) * HH + j], ih[i], il[i]);
        split2(Wh[(size_t)(k0 + i) * HH + j], hh[i], hl[i]);
    }
    size_t off = (size_t)ncol * HH + k0;
    *(uint4*)(g_Wt_hi + off)  = *(uint4*)ih;
    *(uint4*)(g_Wt_lo + off)  = *(uint4*)il;
    *(uint4*)(g_Wht_hi + off) = *(uint4*)hh;
    *(uint4*)(g_Wht_lo + off) = *(uint4*)hl;
    if ((u & 63) == 0) {
        const float* bias = (gate == 0) ? bir : (gate == 1) ? biz : bin;
        g_bias[ncol] = bias[j];
    }
}

// ----------------------------------------------------------------------------
// Prep 3: split init_h into ping-pong buffer 0 (bf16 hi/lo); reset barrier.
// ----------------------------------------------------------------------------
__global__ __launch_bounds__(256) void prep_h_kernel(const float* __restrict__ H0) {
    int u = blockIdx.x * 256 + threadIdx.x;
    if (u == 0) g_bar = 0;
    if (u >= BB * HH / 8) return;
    size_t base = (size_t)u * 8;
    float4 v0 = *(const float4*)(H0 + base);
    float4 v1 = *(const float4*)(H0 + base + 4);
    float xs[8] = {v0.x, v0.y, v0.z, v0.w, v1.x, v1.y, v1.z, v1.w};
    uint16_t hp[8], lp[8];
#pragma unroll
    for (int j = 0; j < 8; ++j) split2(xs[j], hp[j], lp[j]);
    *(uint4*)(g_Hh + base) = *(uint4*)hp;
    *(uint4*)(g_Hl + base) = *(uint4*)lp;
}

// ----------------------------------------------------------------------------
// Input GEMM via mma.sync (fragment math proven R5-R7). New tiling:
// CTA 128M x 128N, 8 warps as 2m x 4n (warp tile 64x32) -> 48 mma per 16 ldsm
// per kc (2x tensor density vs R7). Double-buffered, 1 sync per 32-k chunk.
// Grid (12 n-slabs fastest for L2 A-reuse, 1024 m-tiles).
// ----------------------------------------------------------------------------
#define IG_ABUF (128*40)
#define IG_BBUF (128*40)
#define IG_SMEM_BYTES ((2*(IG_ABUF + IG_ABUF + IG_BBUF + IG_BBUF)) * 2)   // 81920

__global__ __launch_bounds__(256, 1) void input_gemm_mma() {
    extern __shared__ __align__(16) uint16_t ig_sm[];
    uint16_t* Abufh[2]; uint16_t* Abufl[2]; uint16_t* Bbufh[2]; uint16_t* Bbufl[2];
    {
        uint16_t* p = ig_sm;
        Abufh[0] = p; p += IG_ABUF;  Abufl[0] = p; p += IG_ABUF;
        Bbufh[0] = p; p += IG_BBUF;  Bbufl[0] = p; p += IG_BBUF;
        Abufh[1] = p; p += IG_ABUF;  Abufl[1] = p; p += IG_ABUF;
        Bbufh[1] = p; p += IG_BBUF;  Bbufl[1] = p;
    }
    const int tid = threadIdx.x;
    const int w = tid >> 5, l = tid & 31;
    const int n0 = blockIdx.x * 128;    // n fastest for L2 A-reuse
    const int m0 = blockIdx.y * 128;
    const int wm = w >> 2, wn = w & 3;  // 2m x 4n

    float c[4][4][4];
#pragma unroll
    for (int mi = 0; mi < 4; ++mi)
#pragma unroll
        for (int ni = 0; ni < 4; ++ni)
#pragma unroll
            for (int q = 0; q < 4; ++q) c[mi][ni][q] = 0.0f;

    const int ar = tid >> 1, half = tid & 1;   // 128 rows, 2 thr/row (A and B alike)

    uint4 sA[4], sB[4];
#define IG_LDG(kt) {                                                                   \
    const uint16_t* pah = g_Xh + (size_t)(m0 + ar) * HH + (kt) + half * 16;            \
    const uint16_t* pal = g_Xl + (size_t)(m0 + ar) * HH + (kt) + half * 16;            \
    sA[0] = *(const uint4*)pah;       sA[1] = *(const uint4*)(pah + 8);                \
    sA[2] = *(const uint4*)pal;       sA[3] = *(const uint4*)(pal + 8);                \
    const uint16_t* pbh = g_Wt_hi + (size_t)(n0 + ar) * HH + (kt) + half * 16;         \
    const uint16_t* pbl = g_Wt_lo + (size_t)(n0 + ar) * HH + (kt) + half * 16;         \
    sB[0] = *(const uint4*)pbh;       sB[1] = *(const uint4*)(pbh + 8);                \
    sB[2] = *(const uint4*)pbl;       sB[3] = *(const uint4*)(pbl + 8); }

    IG_LDG(0);
    for (int cb = 0; cb < 16; ++cb) {
        uint16_t* Ah = Abufh[cb & 1]; uint16_t* Al = Abufl[cb & 1];
        uint16_t* Bh = Bbufh[cb & 1]; uint16_t* Bl = Bbufl[cb & 1];
        *(uint4*)&Ah[ar * 40 + half * 16]     = sA[0];
        *(uint4*)&Ah[ar * 40 + half * 16 + 8] = sA[1];
        *(uint4*)&Al[ar * 40 + half * 16]     = sA[2];
        *(uint4*)&Al[ar * 40 + half * 16 + 8] = sA[3];
        *(uint4*)&Bh[ar * 40 + half * 16]     = sB[0];
        *(uint4*)&Bh[ar * 40 + half * 16 + 8] = sB[1];
        *(uint4*)&Bl[ar * 40 + half * 16]     = sB[2];
        *(uint4*)&Bl[ar * 40 + half * 16 + 8] = sB[3];
        __syncthreads();
        if (cb < 15) IG_LDG((cb + 1) * 32);

#pragma unroll
        for (int kc = 0; kc < 32; kc += 16) {
            uint32_t bfh[4][2], bfl[4][2];
#pragma unroll
            for (int ni = 0; ni < 4; ++ni) {
                const int nrow = wn * 32 + ni * 8 + (l & 7);
                const int ncolk = kc + ((l >> 3) & 1) * 8;
                ldm_x2(bfh[ni], smem_u32(&Bh[nrow * 40 + ncolk]));
                ldm_x2(bfl[ni], smem_u32(&Bl[nrow * 40 + ncolk]));
            }
#pragma unroll
            for (int mi = 0; mi < 4; ++mi) {
                uint32_t afh[4], afl[4];
                const int row = wm * 64 + mi * 16 + (l & 15);
                const int col = kc + (l >> 4) * 8;
                ldm_x4(afh, smem_u32(&Ah[row * 40 + col]));
                ldm_x4(afl, smem_u32(&Al[row * 40 + col]));
#pragma unroll
                for (int ni = 0; ni < 4; ++ni) {
                    mma16816(c[mi][ni], afh, bfh[ni]);
                    mma16816(c[mi][ni], afh, bfl[ni]);
                    mma16816(c[mi][ni], afl, bfh[ni]);
                }
            }
        }
        if (cb == 15) break;
    }
#undef IG_LDG

    const int g = l >> 2, tq = l & 3;
#pragma unroll
    for (int mi = 0; mi < 4; ++mi)
#pragma unroll
        for (int ni = 0; ni < 4; ++ni) {
            const int ncol = n0 + wn * 32 + ni * 8 + tq * 2;
            const float2 bv = *(const float2*)&g_bias[ncol];
            const int row = m0 + wm * 64 + mi * 16 + g;
            float2 v0 = {c[mi][ni][0] + bv.x, c[mi][ni][1] + bv.y};
            float2 v1 = {c[mi][ni][2] + bv.x, c[mi][ni][3] + bv.y};
            *(float2*)&g_Xg[(size_t)row * G3 + ncol]       = v0;
            *(float2*)&g_Xg[(size_t)(row + 8) * G3 + ncol] = v1;
        }
}

// ----------------------------------------------------------------------------
// Persistent GRU recurrence (proven R6/R7 math). New this round:
//  - h carry kept in REGISTERS (epilogue's prev-h for step t is exactly what
//    this thread computed at t-1; g_Hf buffer deleted — bit-identical values)
//  - Xg[t+1] + resets[t+1] prefetched BEFORE the grid barrier (independent of
//    h), hiding their memory latency under the barrier spin.
// Grid (64 j-tiles, 2 m-halves) = 128 CTAs, 256 thr = 8 warps.
// ----------------------------------------------------------------------------
#define SK_A_STRIDE 72
#define SK_W_STRIDE 520
#define SK_ABUF (128 * SK_A_STRIDE)
#define SK_SMEM_BYTES ((4*SK_ABUF + 2*24*SK_W_STRIDE) * 2)   // 123648

__global__ __launch_bounds__(256) void gru_persistent(
    const int* __restrict__ resets, const float* __restrict__ init_h,
    const float* __restrict__ bhn, float* __restrict__ out) {
    extern __shared__ __align__(16) uint16_t sm[];
    uint16_t* AbH[2]; uint16_t* AbL[2];
    AbH[0] = sm;               AbL[0] = sm + SK_ABUF;
    AbH[1] = sm + 2 * SK_ABUF; AbL[1] = sm + 3 * SK_ABUF;
    uint16_t* Wh = sm + 4 * SK_ABUF;
    uint16_t* Wl = Wh + 24 * SK_W_STRIDE;

    const int tid = threadIdx.x;
    const int w = tid >> 5, l = tid & 31;
    const int j0 = blockIdx.x * 8;     // 0..504
    const int b0 = blockIdx.y * 128;   // 0 or 128
    const int g = l >> 2, tq = l & 3;
    const int C0 = j0 + tq * 2;

    // Load this CTA's W_h slices once: [gate][8 j][512 k].
    for (int u = tid; u < 24 * 64; u += 256) {
        const int row = u >> 6, q = u & 63;
        const int gate = row >> 3;
        const int ncol = gate * 512 + j0 + (row & 7);
        *(uint4*)&Wh[row * SK_W_STRIDE + q * 8] = *(const uint4*)(g_Wht_hi + (size_t)ncol * HH + q * 8);
        *(uint4*)&Wl[row * SK_W_STRIDE + q * 8] = *(const uint4*)(g_Wht_lo + (size_t)ncol * HH + q * 8);
    }
    __syncthreads();

    const int ar = tid >> 1, ahalf = tid & 1;   // A staging: 2 thr/row, 32 k each

    // Register h-carry: prev-h values for this thread's 2 (row, C0..C0+1) cells.
    float2 hc[2];
    bool rzrow[2];
    bool rz_stage;
    float2 pxR[2], pxZ[2], pxN[2];
    {
        const float* xgbase = g_Xg;   // t = 0
#pragma unroll
        for (int rr = 0; rr < 2; ++rr) {
            const int row = b0 + 16 * w + g + rr * 8;
            hc[rr] = *(const float2*)&init_h[(size_t)row * HH + C0];
            rzrow[rr] = resets[row] != 0;
            const float* xr = xgbase + (size_t)row * G3;
            pxR[rr] = *(const float2*)&xr[C0];
            pxZ[rr] = *(const float2*)&xr[512 + C0];
            pxN[rr] = *(const float2*)&xr[1024 + C0];
        }
        rz_stage = resets[b0 + ar] != 0;
    }
    const float2 bh2 = *(const float2*)&bhn[C0];

    for (int t = 0; t < TT; ++t) {
        const int par = t & 1;
        const uint16_t* Hh = g_Hh + (size_t)par * BB * HH;
        const uint16_t* Hl = g_Hl + (size_t)par * BB * HH;

        float c[3][4];
#pragma unroll
        for (int gg = 0; gg < 3; ++gg)
#pragma unroll
            for (int q = 0; q < 4; ++q) c[gg][q] = 0.0f;

        uint4 rh[4], rl[4];
#define SK_LDG(kt) {                                                               \
    const uint4* sh = (const uint4*)(Hh + (size_t)(b0 + ar) * HH + (kt) + ahalf * 32); \
    const uint4* sl = (const uint4*)(Hl + (size_t)(b0 + ar) * HH + (kt) + ahalf * 32); \
    const uint4 z4 = {0u, 0u, 0u, 0u};                                             \
    rh[0] = rz_stage ? z4 : sh[0]; rh[1] = rz_stage ? z4 : sh[1];                  \
    rh[2] = rz_stage ? z4 : sh[2]; rh[3] = rz_stage ? z4 : sh[3];                  \
    rl[0] = rz_stage ? z4 : sl[0]; rl[1] = rz_stage ? z4 : sl[1];                  \
    rl[2] = rz_stage ? z4 : sl[2]; rl[3] = rz_stage ? z4 : sl[3]; }

        SK_LDG(0);
        for (int cb = 0; cb < 8; ++cb) {
            uint16_t* Ah = AbH[cb & 1];
            uint16_t* Al = AbL[cb & 1];
#pragma unroll
            for (int qq = 0; qq < 4; ++qq) {
                *(uint4*)&Ah[ar * SK_A_STRIDE + ahalf * 32 + qq * 8] = rh[qq];
                *(uint4*)&Al[ar * SK_A_STRIDE + ahalf * 32 + qq * 8] = rl[qq];
            }
            __syncthreads();
            if (cb < 7) SK_LDG((cb + 1) * 64);

#pragma unroll
            for (int kc = 0; kc < 64; kc += 16) {
                uint32_t afh[4], afl[4];
                const int arow = (16 * w + (l & 15)) * SK_A_STRIDE + kc + (l >> 4) * 8;
                ldm_x4(afh, smem_u32(&Ah[arow]));
                ldm_x4(afl, smem_u32(&Al[arow]));
#pragma unroll
                for (int gate = 0; gate < 3; ++gate) {
                    const int boff = (gate * 8 + (l & 7)) * SK_W_STRIDE + cb * 64 + kc + ((l >> 3) & 1) * 8;
                    uint32_t bfh[2], bfl[2];
                    ldm_x2(bfh, smem_u32(&Wh[boff]));
                    ldm_x2(bfl, smem_u32(&Wl[boff]));
                    mma16816(c[gate], afh, bfh);
                    mma16816(c[gate], afh, bfl);
                    mma16816(c[gate], afl, bfh);
                }
            }
        }
#undef SK_LDG

        // Fused GRU epilogue: each lane -> 2 rows x 2 cols. Carry in registers.
        {
            float* outt = out + (size_t)t * BB * HH;
            uint16_t* nHh = g_Hh + (size_t)(par ^ 1) * BB * HH;
            uint16_t* nHl = g_Hl + (size_t)(par ^ 1) * BB * HH;
#pragma unroll
            for (int rr = 0; rr < 2; ++rr) {
                const int row = b0 + 16 * w + g + rr * 8;
                float2 hp = hc[rr];
                if (rzrow[rr]) { hp.x = 0.0f; hp.y = 0.0f; }
                const float r0 = sigmoidf_(pxR[rr].x + c[0][rr * 2 + 0]);
                const float r1 = sigmoidf_(pxR[rr].y + c[0][rr * 2 + 1]);
                const float z0 = sigmoidf_(pxZ[rr].x + c[1][rr * 2 + 0]);
                const float z1 = sigmoidf_(pxZ[rr].y + c[1][rr * 2 + 1]);
                const float n0 = tanhf(pxN[rr].x + r0 * (c[2][rr * 2 + 0] + bh2.x));
                const float n1 = tanhf(pxN[rr].y + r1 * (c[2][rr * 2 + 1] + bh2.y));
                const float h0 = (1.0f - z0) * n0 + z0 * hp.x;
                const float h1 = (1.0f - z1) * n1 + z1 * hp.y;
                *(float2*)&outt[(size_t)row * HH + C0] = make_float2(h0, h1);
                hc[rr] = make_float2(h0, h1);     // register carry for step t+1
                uint16_t hh0, hl0, hh1, hl1;
                split2(h0, hh0, hl0);
                split2(h1, hh1, hl1);
                *(uint32_t*)&nHh[(size_t)row * HH + C0] = ((uint32_t)hh1 << 16) | hh0;
                *(uint32_t*)&nHl[(size_t)row * HH + C0] = ((uint32_t)hl1 << 16) | hl0;
            }
        }

        // Prefetch step t+1 operands that do NOT depend on h (hidden by barrier).
        if (t + 1 < TT) {
            const int* rstn = resets + (t + 1) * BB;
            const float* xgbase = g_Xg + (size_t)(t + 1) * BB * G3;
#pragma unroll
            for (int rr = 0; rr < 2; ++rr) {
                const int row = b0 + 16 * w + g + rr * 8;
                rzrow[rr] = rstn[row] != 0;
                const float* xr = xgbase + (size_t)row * G3;
                pxR[rr] = *(const float2*)&xr[C0];
                pxZ[rr] = *(const float2*)&xr[512 + C0];
                pxN[rr] = *(const float2*)&xr[1024 + C0];
            }
            rz_stage = rstn[b0 + ar] != 0;
        }

        // Grid-wide barrier: release writes, arrive, spin on acquire.
        __threadfence();
        __syncthreads();
        if (tid == 0) {
            asm volatile("red.release.gpu.add.u32 [%0], %1;" :: "l"(&g_bar), "r"(1u) : "memory");
            const unsigned target = 128u * (unsigned)(t + 1);
            unsigned v;
            do {
                asm volatile("ld.acquire.gpu.u32 %0, [%1];" : "=r"(v) : "l"(&g_bar) : "memory");
                if (v >= target) break;
                __nanosleep(32);
            } while (true);
        }
        __syncthreads();
    }
}

// ----------------------------------------------------------------------------
// Launch: 3 prep kernels + mma input GEMM + ONE persistent recurrence kernel.
// Graph-capturable (kernel launches only), allocation-free.
// ----------------------------------------------------------------------------
extern "C" void kernel_launch(void* const* d_in, const int* in_sizes, int n_in,
                              void* d_out, int out_size)
{
    const float* ins    = (const float*)d_in[0];
    const int*   resets = (const int*)d_in[1];
    const float* init_h = (const float*)d_in[2];
    const float* W_ir   = (const float*)d_in[3];
    const float* W_iz   = (const float*)d_in[4];
    const float* W_in   = (const float*)d_in[5];
    const float* b_ir   = (const float*)d_in[6];
    const float* b_iz   = (const float*)d_in[7];
    const float* b_in   = (const float*)d_in[8];
    const float* W_hr   = (const float*)d_in[9];
    const float* W_hz   = (const float*)d_in[10];
    const float* W_hn   = (const float*)d_in[11];
    const float* b_hn   = (const float*)d_in[12];
    float* out = (float*)d_out;

    cudaFuncSetAttribute(input_gemm_mma,
                         cudaFuncAttributeMaxDynamicSharedMemorySize, IG_SMEM_BYTES);
    cudaFuncSetAttribute(gru_persistent,
                         cudaFuncAttributeMaxDynamicSharedMemorySize, SK_SMEM_BYTES);

    prep_x_kernel<<<(int)(((size_t)MTOT * HH / 8 + 255) / 256), 256>>>(ins);
    prep_w_kernel<<<(G3 * HH / 8 + 255) / 256, 256>>>(W_ir, W_iz, W_in,
                                                      W_hr, W_hz, W_hn,
                                                      b_ir, b_iz, b_in);
    prep_h_kernel<<<(BB * HH / 8 + 255) / 256, 256>>>(init_h);

    // n-slab fastest: each A m-tile is DRAM-read once, L2-served to 12 n-CTAs.
    input_gemm_mma<<<dim3(G3 / 128, MTOT / 128), 256, IG_SMEM_BYTES>>>();

    gru_persistent<<<dim3(64, 2), 256, SK_SMEM_BYTES>>>(resets, init_h, b_hn, out);
}

// round 9
// speedup vs baseline: 2.4679x; 1.0672x over previous
#include <cuda_runtime.h>
#include <cuda_bf16.h>
#include <cstdint>
#include <cmath>

// Problem dims (fixed by the reference).
#define TT 512
#define BB 256
#define HH 512
#define G3 1536
#define MTOT (TT*BB)   // 131072

// -------------------- device scratch (no cudaMalloc allowed) --------------------
__device__ float    g_Xg[(size_t)MTOT * G3];        // fp32 input-side preactivations
__device__ uint16_t g_Xh[(size_t)MTOT * HH];        // bf16 hi of ins
__device__ uint16_t g_Xl[(size_t)MTOT * HH];        // bf16 lo of ins
__device__ uint16_t g_Wt_hi[(size_t)G3 * HH];       // input weights, transposed [ncol][k]
__device__ uint16_t g_Wt_lo[(size_t)G3 * HH];
__device__ uint16_t g_Wht_hi[(size_t)G3 * HH];      // hidden weights, transposed [ncol][k]
__device__ uint16_t g_Wht_lo[(size_t)G3 * HH];
__device__ uint16_t g_Hh[2 * BB * HH];              // ping-pong split h (hi)
__device__ uint16_t g_Hl[2 * BB * HH];              // ping-pong split h (lo)
__device__ float    g_bias[G3];
__device__ unsigned int g_bar;                      // persistent-kernel grid barrier

// -------------------- helpers --------------------
__device__ __forceinline__ uint32_t smem_u32(const void* p) {
    uint32_t a;
    asm("{ .reg .u64 t; cvta.to.shared.u64 t, %1; cvt.u32.u64 %0, t; }" : "=r"(a) : "l"(p));
    return a;
}
__device__ __forceinline__ void ldm_x4(uint32_t* r, uint32_t addr) {
    asm volatile("ldmatrix.sync.aligned.m8n8.x4.shared.b16 {%0,%1,%2,%3}, [%4];"
                 : "=r"(r[0]), "=r"(r[1]), "=r"(r[2]), "=r"(r[3]) : "r"(addr));
}
__device__ __forceinline__ void ldm_x2(uint32_t* r, uint32_t addr) {
    asm volatile("ldmatrix.sync.aligned.m8n8.x2.shared.b16 {%0,%1}, [%2];"
                 : "=r"(r[0]), "=r"(r[1]) : "r"(addr));
}
// D(16x8,f32) += A(16x16 bf16 row) * B(16x8 bf16 col)
__device__ __forceinline__ void mma16816(float* c, const uint32_t* a, const uint32_t* b) {
    asm volatile("mma.sync.aligned.m16n8k16.row.col.f32.bf16.bf16.f32 "
                 "{%0,%1,%2,%3}, {%4,%5,%6,%7}, {%8,%9}, {%0,%1,%2,%3};"
                 : "+f"(c[0]), "+f"(c[1]), "+f"(c[2]), "+f"(c[3])
                 : "r"(a[0]), "r"(a[1]), "r"(a[2]), "r"(a[3]), "r"(b[0]), "r"(b[1]));
}
__device__ __forceinline__ void split2(float x, uint16_t& h, uint16_t& l) {
    __nv_bfloat16 hb = __float2bfloat16_rn(x);
    __nv_bfloat16 lb = __float2bfloat16_rn(x - __bfloat162float(hb));
    h = __bfloat16_as_ushort(hb);
    l = __bfloat16_as_ushort(lb);
}
__device__ __forceinline__ float sigmoidf_(float x) { return 1.0f / (1.0f + expf(-x)); }

// ----------------------------------------------------------------------------
// Prep 1: split ins fp32 -> bf16 hi/lo, row-major [MTOT][512].
// ----------------------------------------------------------------------------
__global__ __launch_bounds__(256) void prep_x_kernel(const float* __restrict__ X) {
    size_t u = (size_t)blockIdx.x * 256 + threadIdx.x;
    if (u >= (size_t)MTOT * HH / 8) return;
    size_t base = u * 8;
    float4 v0 = *(const float4*)(X + base);
    float4 v1 = *(const float4*)(X + base + 4);
    float xs[8] = {v0.x, v0.y, v0.z, v0.w, v1.x, v1.y, v1.z, v1.w};
    uint16_t hp[8], lp[8];
#pragma unroll
    for (int j = 0; j < 8; ++j) split2(xs[j], hp[j], lp[j]);
    *(uint4*)(g_Xh + base) = *(uint4*)hp;
    *(uint4*)(g_Xl + base) = *(uint4*)lp;
}

// ----------------------------------------------------------------------------
// Prep 2: transpose + split BOTH weight sets: Wt[ncol][k] = W_gate[k][j].
// ----------------------------------------------------------------------------
__global__ __launch_bounds__(256) void prep_w_kernel(
    const float* __restrict__ Wir, const float* __restrict__ Wiz, const float* __restrict__ Win,
    const float* __restrict__ Whr, const float* __restrict__ Whz, const float* __restrict__ Whn,
    const float* __restrict__ bir, const float* __restrict__ biz, const float* __restrict__ bin) {
    int u = blockIdx.x * 256 + threadIdx.x;
    if (u >= G3 * HH / 8) return;
    int ncol = u >> 6;
    int k0 = (u & 63) * 8;
    int gate = ncol >> 9, j = ncol & 511;
    const float* Wi = (gate == 0) ? Wir : (gate == 1) ? Wiz : Win;
    const float* Wh = (gate == 0) ? Whr : (gate == 1) ? Whz : Whn;
    uint16_t ih[8], il[8], hh[8], hl[8];
#pragma unroll
    for (int i = 0; i < 8; ++i) {
        split2(Wi[(size_t)(k0 + i) * HH + j], ih[i], il[i]);
        split2(Wh[(size_t)(k0 + i) * HH + j], hh[i], hl[i]);
    }
    size_t off = (size_t)ncol * HH + k0;
    *(uint4*)(g_Wt_hi + off)  = *(uint4*)ih;
    *(uint4*)(g_Wt_lo + off)  = *(uint4*)il;
    *(uint4*)(g_Wht_hi + off) = *(uint4*)hh;
    *(uint4*)(g_Wht_lo + off) = *(uint4*)hl;
    if ((u & 63) == 0) {
        const float* bias = (gate == 0) ? bir : (gate == 1) ? biz : bin;
        g_bias[ncol] = bias[j];
    }
}

// ----------------------------------------------------------------------------
// Prep 3: split init_h into ping-pong buffer 0 (bf16 hi/lo); reset barrier.
// ----------------------------------------------------------------------------
__global__ __launch_bounds__(256) void prep_h_kernel(const float* __restrict__ H0) {
    int u = blockIdx.x * 256 + threadIdx.x;
    if (u == 0) g_bar = 0;
    if (u >= BB * HH / 8) return;
    size_t base = (size_t)u * 8;
    float4 v0 = *(const float4*)(H0 + base);
    float4 v1 = *(const float4*)(H0 + base + 4);
    float xs[8] = {v0.x, v0.y, v0.z, v0.w, v1.x, v1.y, v1.z, v1.w};
    uint16_t hp[8], lp[8];
#pragma unroll
    for (int j = 0; j < 8; ++j) split2(xs[j], hp[j], lp[j]);
    *(uint4*)(g_Hh + base) = *(uint4*)hp;
    *(uint4*)(g_Hl + base) = *(uint4*)lp;
}

// ----------------------------------------------------------------------------
// Input GEMM via mma.sync (math proven R5-R8, accumulation order unchanged).
// NEW: 512 threads, 16 warps as 4m x 4n (warp tile 32x32) -> 4 warps/SMSP.
// K-chunk 64 (8 syncs), double-buffered, 144KB smem. Grid (12 n fastest, 1024 m).
// ----------------------------------------------------------------------------
#define IG_STRIDE 72
#define IG_BUF (128*IG_STRIDE)
#define IG_SMEM_BYTES (8 * IG_BUF * 2)   // 147456

__global__ __launch_bounds__(512, 1) void input_gemm_mma() {
    extern __shared__ __align__(16) uint16_t ig_sm[];
    uint16_t* Abufh[2]; uint16_t* Abufl[2]; uint16_t* Bbufh[2]; uint16_t* Bbufl[2];
    {
        uint16_t* p = ig_sm;
        Abufh[0] = p; p += IG_BUF;  Abufl[0] = p; p += IG_BUF;
        Bbufh[0] = p; p += IG_BUF;  Bbufl[0] = p; p += IG_BUF;
        Abufh[1] = p; p += IG_BUF;  Abufl[1] = p; p += IG_BUF;
        Bbufh[1] = p; p += IG_BUF;  Bbufl[1] = p;
    }
    const int tid = threadIdx.x;
    const int w = tid >> 5, l = tid & 31;
    const int n0 = blockIdx.x * 128;    // n fastest for L2 A-reuse
    const int m0 = blockIdx.y * 128;
    const int wm = w >> 2, wn = w & 3;  // 4m x 4n, warp tile 32x32

    float c[2][4][4];
#pragma unroll
    for (int mi = 0; mi < 2; ++mi)
#pragma unroll
        for (int ni = 0; ni < 4; ++ni)
#pragma unroll
            for (int q = 0; q < 4; ++q) c[mi][ni][q] = 0.0f;

    const int ar = tid >> 2, seg = tid & 3;   // 128 rows, 4 thr/row (16 k each)

    uint4 sA[4], sB[4];
#define IG_LDG(kt) {                                                                   \
    const uint16_t* pah = g_Xh + (size_t)(m0 + ar) * HH + (kt) + seg * 16;             \
    const uint16_t* pal = g_Xl + (size_t)(m0 + ar) * HH + (kt) + seg * 16;             \
    sA[0] = *(const uint4*)pah;       sA[1] = *(const uint4*)(pah + 8);                \
    sA[2] = *(const uint4*)pal;       sA[3] = *(const uint4*)(pal + 8);                \
    const uint16_t* pbh = g_Wt_hi + (size_t)(n0 + ar) * HH + (kt) + seg * 16;          \
    const uint16_t* pbl = g_Wt_lo + (size_t)(n0 + ar) * HH + (kt) + seg * 16;          \
    sB[0] = *(const uint4*)pbh;       sB[1] = *(const uint4*)(pbh + 8);                \
    sB[2] = *(const uint4*)pbl;       sB[3] = *(const uint4*)(pbl + 8); }

    IG_LDG(0);
    for (int cb = 0; cb < 8; ++cb) {
        uint16_t* Ah = Abufh[cb & 1]; uint16_t* Al = Abufl[cb & 1];
        uint16_t* Bh = Bbufh[cb & 1]; uint16_t* Bl = Bbufl[cb & 1];
        *(uint4*)&Ah[ar * IG_STRIDE + seg * 16]     = sA[0];
        *(uint4*)&Ah[ar * IG_STRIDE + seg * 16 + 8] = sA[1];
        *(uint4*)&Al[ar * IG_STRIDE + seg * 16]     = sA[2];
        *(uint4*)&Al[ar * IG_STRIDE + seg * 16 + 8] = sA[3];
        *(uint4*)&Bh[ar * IG_STRIDE + seg * 16]     = sB[0];
        *(uint4*)&Bh[ar * IG_STRIDE + seg * 16 + 8] = sB[1];
        *(uint4*)&Bl[ar * IG_STRIDE + seg * 16]     = sB[2];
        *(uint4*)&Bl[ar * IG_STRIDE + seg * 16 + 8] = sB[3];
        __syncthreads();
        if (cb < 7) IG_LDG((cb + 1) * 64);

#pragma unroll
        for (int kc = 0; kc < 64; kc += 16) {
            uint32_t bfh[4][2], bfl[4][2];
#pragma unroll
            for (int ni = 0; ni < 4; ++ni) {
                const int nrow = wn * 32 + ni * 8 + (l & 7);
                const int ncolk = kc + ((l >> 3) & 1) * 8;
                ldm_x2(bfh[ni], smem_u32(&Bh[nrow * IG_STRIDE + ncolk]));
                ldm_x2(bfl[ni], smem_u32(&Bl[nrow * IG_STRIDE + ncolk]));
            }
#pragma unroll
            for (int mi = 0; mi < 2; ++mi) {
                uint32_t afh[4], afl[4];
                const int row = wm * 32 + mi * 16 + (l & 15);
                const int col = kc + (l >> 4) * 8;
                ldm_x4(afh, smem_u32(&Ah[row * IG_STRIDE + col]));
                ldm_x4(afl, smem_u32(&Al[row * IG_STRIDE + col]));
#pragma unroll
                for (int ni = 0; ni < 4; ++ni) {
                    mma16816(c[mi][ni], afh, bfh[ni]);
                    mma16816(c[mi][ni], afh, bfl[ni]);
                    mma16816(c[mi][ni], afl, bfh[ni]);
                }
            }
        }
        if (cb == 7) break;
    }
#undef IG_LDG

    const int g = l >> 2, tq = l & 3;
#pragma unroll
    for (int mi = 0; mi < 2; ++mi)
#pragma unroll
        for (int ni = 0; ni < 4; ++ni) {
            const int ncol = n0 + wn * 32 + ni * 8 + tq * 2;
            const float2 bv = *(const float2*)&g_bias[ncol];
            const int row = m0 + wm * 32 + mi * 16 + g;
            float2 v0 = {c[mi][ni][0] + bv.x, c[mi][ni][1] + bv.y};
            float2 v1 = {c[mi][ni][2] + bv.x, c[mi][ni][3] + bv.y};
            *(float2*)&g_Xg[(size_t)row * G3 + ncol]       = v0;
            *(float2*)&g_Xg[(size_t)(row + 8) * G3 + ncol] = v1;
        }
}

// ----------------------------------------------------------------------------
// Persistent GRU recurrence (math proven R6-R8). NEW: 512 threads, 16 warps
// = 8 m-warps x 2 k-halves (interleaved 16-k groups within each 64-chunk so
// both halves consume every staged chunk). End-of-step 2-way partial-sum
// reduction through reused A-buffer smem; epilogue + register h-carry in the
// half-0 warps. Grid (64 j-tiles, 2 m-halves) = 128 CTAs.
// ----------------------------------------------------------------------------
#define SK_A_STRIDE 72
#define SK_W_STRIDE 520
#define SK_ABUF (128 * SK_A_STRIDE)
#define SK_SMEM_BYTES ((4*SK_ABUF + 2*24*SK_W_STRIDE) * 2)   // 123648

__global__ __launch_bounds__(512) void gru_persistent(
    const int* __restrict__ resets, const float* __restrict__ init_h,
    const float* __restrict__ bhn, float* __restrict__ out) {
    extern __shared__ __align__(16) uint16_t sm[];
    uint16_t* AbH[2]; uint16_t* AbL[2];
    AbH[0] = sm;               AbL[0] = sm + SK_ABUF;
    AbH[1] = sm + 2 * SK_ABUF; AbL[1] = sm + 3 * SK_ABUF;
    uint16_t* Wh = sm + 4 * SK_ABUF;
    uint16_t* Wl = Wh + 24 * SK_W_STRIDE;
    float* red_buf = (float*)sm;       // reused A-buffer (after MMA reads done)

    const int tid = threadIdx.x;
    const int w = tid >> 5, l = tid & 31;
    const int wm = w & 7, wk = w >> 3;   // m-warp 0..7, k-half 0..1
    const int j0 = blockIdx.x * 8;       // 0..504
    const int b0 = blockIdx.y * 128;     // 0 or 128
    const int g = l >> 2, tq = l & 3;
    const int C0 = j0 + tq * 2;

    // Load this CTA's W_h slices once: [gate][8 j][512 k].
    for (int u = tid; u < 24 * 64; u += 512) {
        const int row = u >> 6, q = u & 63;
        const int gate = row >> 3;
        const int ncol = gate * 512 + j0 + (row & 7);
        *(uint4*)&Wh[row * SK_W_STRIDE + q * 8] = *(const uint4*)(g_Wht_hi + (size_t)ncol * HH + q * 8);
        *(uint4*)&Wl[row * SK_W_STRIDE + q * 8] = *(const uint4*)(g_Wht_lo + (size_t)ncol * HH + q * 8);
    }
    __syncthreads();

    const int ar = tid >> 2, aq = tid & 3;   // A staging: 4 thr/row, 16 k each

    // Register h-carry + epilogue prefetch (half-0 warps only use these).
    float2 hc[2];
    bool rzrow[2];
    bool rz_stage;
    float2 pxR[2], pxZ[2], pxN[2];
    {
        if (wk == 0) {
#pragma unroll
            for (int rr = 0; rr < 2; ++rr) {
                const int row = b0 + 16 * wm + g + rr * 8;
                hc[rr] = *(const float2*)&init_h[(size_t)row * HH + C0];
                rzrow[rr] = resets[row] != 0;
                const float* xr = g_Xg + (size_t)row * G3;
                pxR[rr] = *(const float2*)&xr[C0];
                pxZ[rr] = *(const float2*)&xr[512 + C0];
                pxN[rr] = *(const float2*)&xr[1024 + C0];
            }
        }
        rz_stage = resets[b0 + ar] != 0;
    }
    const float2 bh2 = *(const float2*)&bhn[C0];

    for (int t = 0; t < TT; ++t) {
        const int par = t & 1;
        const uint16_t* Hh = g_Hh + (size_t)par * BB * HH;
        const uint16_t* Hl = g_Hl + (size_t)par * BB * HH;

        float c[3][4];
#pragma unroll
        for (int gg = 0; gg < 3; ++gg)
#pragma unroll
            for (int q = 0; q < 4; ++q) c[gg][q] = 0.0f;

        uint4 rh[2], rl[2];
#define SK_LDG(kt) {                                                               \
    const uint16_t* sh = Hh + (size_t)(b0 + ar) * HH + (kt) + aq * 16;             \
    const uint16_t* sl = Hl + (size_t)(b0 + ar) * HH + (kt) + aq * 16;             \
    const uint4 z4 = {0u, 0u, 0u, 0u};                                             \
    rh[0] = rz_stage ? z4 : *(const uint4*)sh;                                     \
    rh[1] = rz_stage ? z4 : *(const uint4*)(sh + 8);                               \
    rl[0] = rz_stage ? z4 : *(const uint4*)sl;                                     \
    rl[1] = rz_stage ? z4 : *(const uint4*)(sl + 8); }

        SK_LDG(0);
        for (int cb = 0; cb < 8; ++cb) {
            uint16_t* Ah = AbH[cb & 1];
            uint16_t* Al = AbL[cb & 1];
            *(uint4*)&Ah[ar * SK_A_STRIDE + aq * 16]     = rh[0];
            *(uint4*)&Ah[ar * SK_A_STRIDE + aq * 16 + 8] = rh[1];
            *(uint4*)&Al[ar * SK_A_STRIDE + aq * 16]     = rl[0];
            *(uint4*)&Al[ar * SK_A_STRIDE + aq * 16 + 8] = rl[1];
            __syncthreads();
            if (cb < 7) SK_LDG((cb + 1) * 64);

            // k-half wk takes 16-k groups {wk*16, wk*16+32} inside the chunk.
#pragma unroll
            for (int hkc = 0; hkc < 2; ++hkc) {
                const int kc = wk * 16 + hkc * 32;
                uint32_t afh[4], afl[4];
                const int arow = (16 * wm + (l & 15)) * SK_A_STRIDE + kc + (l >> 4) * 8;
                ldm_x4(afh, smem_u32(&Ah[arow]));
                ldm_x4(afl, smem_u32(&Al[arow]));
#pragma unroll
                for (int gate = 0; gate < 3; ++gate) {
                    const int boff = (gate * 8 + (l & 7)) * SK_W_STRIDE + cb * 64 + kc + ((l >> 3) & 1) * 8;
                    uint32_t bfh[2], bfl[2];
                    ldm_x2(bfh, smem_u32(&Wh[boff]));
                    ldm_x2(bfl, smem_u32(&Wl[boff]));
                    mma16816(c[gate], afh, bfh);
                    mma16816(c[gate], afh, bfl);
                    mma16816(c[gate], afl, bfh);
                }
            }
        }
#undef SK_LDG
        __syncthreads();   // all MMA smem reads done; A-buffer reusable

        // 2-way partial reduction: half-1 writes partials, half-0 adds.
        if (wk == 1) {
            float* dst = red_buf + (wm * 32 + l) * 12;
#pragma unroll
            for (int gg = 0; gg < 3; ++gg)
#pragma unroll
                for (int q = 0; q < 4; ++q) dst[gg * 4 + q] = c[gg][q];
        }
        __syncthreads();

        if (wk == 0) {
            const float* src = red_buf + (wm * 32 + l) * 12;
#pragma unroll
            for (int gg = 0; gg < 3; ++gg)
#pragma unroll
                for (int q = 0; q < 4; ++q) c[gg][q] += src[gg * 4 + q];

            // Fused GRU epilogue: 2 rows x 2 cols per thread; carry in registers.
            float* outt = out + (size_t)t * BB * HH;
            uint16_t* nHh = g_Hh + (size_t)(par ^ 1) * BB * HH;
            uint16_t* nHl = g_Hl + (size_t)(par ^ 1) * BB * HH;
#pragma unroll
            for (int rr = 0; rr < 2; ++rr) {
                const int row = b0 + 16 * wm + g + rr * 8;
                float2 hp = hc[rr];
                if (rzrow[rr]) { hp.x = 0.0f; hp.y = 0.0f; }
                const float r0 = sigmoidf_(pxR[rr].x + c[0][rr * 2 + 0]);
                const float r1 = sigmoidf_(pxR[rr].y + c[0][rr * 2 + 1]);
                const float z0 = sigmoidf_(pxZ[rr].x + c[1][rr * 2 + 0]);
                const float z1 = sigmoidf_(pxZ[rr].y + c[1][rr * 2 + 1]);
                const float n0 = tanhf(pxN[rr].x + r0 * (c[2][rr * 2 + 0] + bh2.x));
                const float n1 = tanhf(pxN[rr].y + r1 * (c[2][rr * 2 + 1] + bh2.y));
                const float h0 = (1.0f - z0) * n0 + z0 * hp.x;
                const float h1 = (1.0f - z1) * n1 + z1 * hp.y;
                *(float2*)&outt[(size_t)row * HH + C0] = make_float2(h0, h1);
                hc[rr] = make_float2(h0, h1);
                uint16_t hh0, hl0, hh1, hl1;
                split2(h0, hh0, hl0);
                split2(h1, hh1, hl1);
                *(uint32_t*)&nHh[(size_t)row * HH + C0] = ((uint32_t)hh1 << 16) | hh0;
                *(uint32_t*)&nHl[(size_t)row * HH + C0] = ((uint32_t)hl1 << 16) | hl0;
            }
        }

        // Prefetch step t+1 operands independent of h (hidden by the barrier).
        if (t + 1 < TT) {
            const int* rstn = resets + (t + 1) * BB;
            if (wk == 0) {
                const float* xgbase = g_Xg + (size_t)(t + 1) * BB * G3;
#pragma unroll
                for (int rr = 0; rr < 2; ++rr) {
                    const int row = b0 + 16 * wm + g + rr * 8;
                    rzrow[rr] = rstn[row] != 0;
                    const float* xr = xgbase + (size_t)row * G3;
                    pxR[rr] = *(const float2*)&xr[C0];
                    pxZ[rr] = *(const float2*)&xr[512 + C0];
                    pxN[rr] = *(const float2*)&xr[1024 + C0];
                }
            }
            rz_stage = rstn[b0 + ar] != 0;
        }

        // Grid-wide barrier: release writes, arrive, spin on acquire.
        __threadfence();
        __syncthreads();
        if (tid == 0) {
            asm volatile("red.release.gpu.add.u32 [%0], %1;" :: "l"(&g_bar), "r"(1u) : "memory");
            const unsigned target = 128u * (unsigned)(t + 1);
            unsigned v;
            do {
                asm volatile("ld.acquire.gpu.u32 %0, [%1];" : "=r"(v) : "l"(&g_bar) : "memory");
                if (v >= target) break;
                __nanosleep(32);
            } while (true);
        }
        __syncthreads();
    }
}

// ----------------------------------------------------------------------------
// Launch: 3 prep kernels + mma input GEMM + ONE persistent recurrence kernel.
// Graph-capturable (kernel launches only), allocation-free.
// ----------------------------------------------------------------------------
extern "C" void kernel_launch(void* const* d_in, const int* in_sizes, int n_in,
                              void* d_out, int out_size)
{
    const float* ins    = (const float*)d_in[0];
    const int*   resets = (const int*)d_in[1];
    const float* init_h = (const float*)d_in[2];
    const float* W_ir   = (const float*)d_in[3];
    const float* W_iz   = (const float*)d_in[4];
    const float* W_in   = (const float*)d_in[5];
    const float* b_ir   = (const float*)d_in[6];
    const float* b_iz   = (const float*)d_in[7];
    const float* b_in   = (const float*)d_in[8];
    const float* W_hr   = (const float*)d_in[9];
    const float* W_hz   = (const float*)d_in[10];
    const float* W_hn   = (const float*)d_in[11];
    const float* b_hn   = (const float*)d_in[12];
    float* out = (float*)d_out;

    cudaFuncSetAttribute(input_gemm_mma,
                         cudaFuncAttributeMaxDynamicSharedMemorySize, IG_SMEM_BYTES);
    cudaFuncSetAttribute(gru_persistent,
                         cudaFuncAttributeMaxDynamicSharedMemorySize, SK_SMEM_BYTES);

    prep_x_kernel<<<(int)(((size_t)MTOT * HH / 8 + 255) / 256), 256>>>(ins);
    prep_w_kernel<<<(G3 * HH / 8 + 255) / 256, 256>>>(W_ir, W_iz, W_in,
                                                      W_hr, W_hz, W_hn,
                                                      b_ir, b_iz, b_in);
    prep_h_kernel<<<(BB * HH / 8 + 255) / 256, 256>>>(init_h);

    // n-slab fastest: each A m-tile is DRAM-read once, L2-served to 12 n-CTAs.
    input_gemm_mma<<<dim3(G3 / 128, MTOT / 128), 512, IG_SMEM_BYTES>>>();

    gru_persistent<<<dim3(64, 2), 512, SK_SMEM_BYTES>>>(resets, init_h, b_hn, out);
}